// round 13
// baseline (speedup 1.0000x reference)
#include <cuda_runtime.h>
#include <cuda_fp16.h>

#define NN 50000
#define NE 800000
#define EPS 1e-5f
#define NBLK 49   // ceil(NN/1024)

// ---------------- static scratch ----------------
__device__ __align__(16) float  g_x[NN * 64];       // node features
__device__ __align__(16) __half g_PQ[NN * 256];     // per-node [pP|pQ|cP|cQ] fp16
__device__ __align__(16) __half g_z2p[NE * 64];     // parent z2 (fp16), CSR(dst) order
__device__ __align__(16) __half g_z2c[NE * 64];     // child z2 (fp16), CSR(src) order
__device__ __align__(16) float  g_aggP[NN * 64];    // deg-normalized parent agg
__device__ __align__(16) float  g_aggC[NN * 64];
__device__ int   g_cntP[NN], g_cntC[NN];            // degree counts, then fill cursors
__device__ int   g_offP[NN + 1], g_offC[NN + 1];    // CSR offsets
__device__ __align__(8) int2 g_eP[NE];              // parent-dir (i=dst, j=src), sorted by i
__device__ __align__(8) int2 g_eC[NE];              // child-dir (i=src, j=dst), sorted by i
__device__ float g_dinvP[NN], g_dinvC[NN];
__device__ __align__(16) uint2 g_Bf[2048];          // pre-packed W2 MMA fragments (p|c)
__device__ int   g_bsum[2 * NBLK];                  // scan block sums
// [0:64]S1p [64:128]S1c [128:192]Q1p [192:256]Q1c
// [256:320]A1p [320:384]A1c [384:448]D1p [448:512]D1c
// [512:576]S2p [576:640]S2c [640:704]Q2p [704:768]Q2c
// [768:832]A2p [832:896]A2c [896:960]D2p [960:1024]D2c
__device__ __align__(16) float g_stats[1024];

__device__ __forceinline__ unsigned pack_h2(float a, float b) {
    __half2 h = __floats2half2_rn(a, b);
    return *reinterpret_cast<unsigned*>(&h);
}
__device__ __forceinline__ float2 upk(unsigned u) {
    return __half22float2(*reinterpret_cast<__half2*>(&u));
}

__device__ __forceinline__ void mma_f16(float* c, const unsigned* a, unsigned b0, unsigned b1) {
    asm volatile(
        "mma.sync.aligned.m16n8k16.row.col.f32.f16.f16.f32 "
        "{%0,%1,%2,%3}, {%4,%5,%6,%7}, {%8,%9}, {%0,%1,%2,%3};"
        : "+f"(c[0]), "+f"(c[1]), "+f"(c[2]), "+f"(c[3])
        : "r"(a[0]), "r"(a[1]), "r"(a[2]), "r"(a[3]), "r"(b0), "r"(b1));
}

// ---------------- zero counters + stats ----------------
__global__ void k_zero() {
    int t = blockIdx.x * blockDim.x + threadIdx.x;
    if (t < NN) { g_cntP[t] = 0; g_cntC[t] = 0; }
    if (t < 1024) g_stats[t] = 0.f;
}

// ---------------- fused setup: embed || degree || pack ----------------
__global__ void k_init(const int* __restrict__ nodes, const float* __restrict__ emb,
                       const int* __restrict__ src, const int* __restrict__ dst,
                       const float* __restrict__ pW2, const float* __restrict__ cW2) {
    int b = blockIdx.x;
    int tid = threadIdx.x;
    if (b < 3125) {
        int t = b * 256 + tid;
        int n = t >> 4, q = t & 15;
        reinterpret_cast<float4*>(g_x)[t] =
            reinterpret_cast<const float4*>(emb)[nodes[n] * 16 + q];
    } else if (b < 6250) {
        int e = (b - 3125) * 256 + tid;
        atomicAdd(&g_cntP[dst[e]], 1);
        atomicAdd(&g_cntC[src[e]], 1);
    } else {
        int t = (b - 6250) * 256 + tid;
        if (t < 2048) {
            int dir = t >> 10, u = t & 1023;
            int kk = u >> 8, nt = (u >> 5) & 7, ln = u & 31;
            int k0 = kk * 16 + (ln & 3) * 2;
            int n  = nt * 8 + (ln >> 2);
            const float* W = dir ? cW2 : pW2;
            uint2 v;
            v.x = pack_h2(W[k0 * 64 + n],       W[(k0 + 1) * 64 + n]);
            v.y = pack_h2(W[(k0 + 8) * 64 + n], W[(k0 + 9) * 64 + n]);
            g_Bf[t] = v;
        }
    }
}

// ---------------- parallel scan phase A: per-chunk block sums ----------------
__global__ void k_scanA() {
    __shared__ int ws[32];
    int half = blockIdx.y;
    int idx = blockIdx.x * 1024 + threadIdx.x;
    int lane = threadIdx.x & 31, w = threadIdx.x >> 5;
    const int* cnt = half ? g_cntC : g_cntP;
    int v = (idx < NN) ? cnt[idx] : 0;
#pragma unroll
    for (int o = 16; o > 0; o >>= 1) v += __shfl_down_sync(0xffffffff, v, o);
    if (lane == 0) ws[w] = v;
    __syncthreads();
    if (threadIdx.x < 32) {
        int s = ws[threadIdx.x];
#pragma unroll
        for (int o = 16; o > 0; o >>= 1) s += __shfl_down_sync(0xffffffff, s, o);
        if (threadIdx.x == 0) g_bsum[half * NBLK + blockIdx.x] = s;
    }
}

// ---------------- parallel scan phase B: 64-wide Hillis-Steele over block sums ----------------
__global__ void k_scanB() {
    __shared__ int sh[2][64];
    int t = threadIdx.x;           // 128 threads
    int half = t >> 6, i = t & 63;
    int v = (i < NBLK) ? g_bsum[half * NBLK + i] : 0;
    sh[half][i] = v;
    __syncthreads();
#pragma unroll
    for (int o = 1; o < 64; o <<= 1) {
        int add = (i >= o) ? sh[half][i - o] : 0;
        __syncthreads();
        sh[half][i] += add;
        __syncthreads();
    }
    if (i < NBLK) g_bsum[half * NBLK + i] = sh[half][i] - v;  // exclusive
    if (i == NBLK - 1) (half ? g_offC : g_offP)[NN] = sh[half][NBLK - 1];
}

// ---------------- parallel scan phase C: per-chunk scan + base; dinv; zero cursors ----------------
__global__ void k_scanC() {
    __shared__ int wsum[32];
    int half = blockIdx.y;
    int idx = blockIdx.x * 1024 + threadIdx.x;
    int lane = threadIdx.x & 31, w = threadIdx.x >> 5;
    int* cnt = half ? g_cntC : g_cntP;
    int* off = half ? g_offC : g_offP;
    float* dinv = half ? g_dinvC : g_dinvP;
    int v = (idx < NN) ? cnt[idx] : 0;
    int x = v;
#pragma unroll
    for (int o = 1; o < 32; o <<= 1) {
        int y = __shfl_up_sync(0xffffffff, x, o);
        if (lane >= o) x += y;
    }
    if (lane == 31) wsum[w] = x;
    __syncthreads();
    if (w == 0) {
        int s = wsum[lane];
#pragma unroll
        for (int o = 1; o < 32; o <<= 1) {
            int y = __shfl_up_sync(0xffffffff, s, o);
            if (lane >= o) s += y;
        }
        wsum[lane] = s;
    }
    __syncthreads();
    int incl = x + (w ? wsum[w - 1] : 0);
    int excl = incl - v + g_bsum[half * NBLK + blockIdx.x];
    if (idx < NN) {
        off[idx] = excl;
        dinv[idx] = v ? (1.f / v) : 0.f;
        cnt[idx] = 0;
    }
}

// fill direction-sorted edge lists (packed int2)
__global__ void k_fill(const int* __restrict__ src, const int* __restrict__ dst) {
    int e = blockIdx.x * blockDim.x + threadIdx.x;
    if (e < NE) {
        int s = src[e], d = dst[e];
        int p = atomicAdd(&g_cntP[d], 1);
        g_eP[g_offP[d] + p] = make_int2(d, s);
        int c = atomicAdd(&g_cntC[s], 1);
        g_eC[g_offC[s] + c] = make_int2(s, d);
    }
}

// ---------------- PQ = x @ [pW1t|pW1b|cW1t|cW1b]  (first iteration only) ----------------
__global__ void k_pq_dual(const float* __restrict__ pW1, const float* __restrict__ cW1) {
    __shared__ float As[64][68];
    __shared__ float Bs[64][64];
    int tid = threadIdx.x;
    int tx = tid & 15, ty = tid >> 4;
    int nb = blockIdx.x * 64;

    for (int t = tid; t < 1024; t += 256) {
        int r = t >> 4, q = t & 15;
        float4 v = make_float4(0.f, 0.f, 0.f, 0.f);
        if (nb + r < NN) v = reinterpret_cast<const float4*>(g_x)[(nb + r) * 16 + q];
        As[r][q * 4 + 0] = v.x; As[r][q * 4 + 1] = v.y;
        As[r][q * 4 + 2] = v.z; As[r][q * 4 + 3] = v.w;
    }
    for (int cc = 0; cc < 4; cc++) {
        __syncthreads();
        const float* W = (cc < 2) ? pW1 : cW1;
        int koff = (cc & 1) ? 64 : 0;
        for (int t = tid; t < 4096; t += 256) {
            int k = t >> 6, c = t & 63;
            Bs[k][c] = W[(koff + k) * 64 + c];
        }
        __syncthreads();
        float acc[4][4] = {};
#pragma unroll 8
        for (int k = 0; k < 64; k++) {
            float a[4];
#pragma unroll
            for (int r = 0; r < 4; r++) a[r] = As[ty * 4 + r][k];
            float4 b = *reinterpret_cast<float4*>(&Bs[k][tx * 4]);
#pragma unroll
            for (int r = 0; r < 4; r++) {
                acc[r][0] += a[r] * b.x; acc[r][1] += a[r] * b.y;
                acc[r][2] += a[r] * b.z; acc[r][3] += a[r] * b.w;
            }
        }
#pragma unroll
        for (int r = 0; r < 4; r++) {
            int row = nb + ty * 4 + r;
            if (row < NN) {
                uint2 o;
                o.x = pack_h2(acc[r][0], acc[r][1]);
                o.y = pack_h2(acc[r][2], acc[r][3]);
                reinterpret_cast<uint2*>(g_PQ)[row * 64 + cc * 16 + tx] = o;
            }
        }
    }
}

// ---------------- z1 stats, both directions, contiguous chunks, 8-edge unroll ----------------
__global__ void k_stats1_dual() {
    __shared__ float red[256];
    int tid = threadIdx.x;
    if (tid < 256) red[tid] = 0.f;
    __syncthreads();
    int lane = tid & 31;
    int gw = (blockIdx.x * blockDim.x + tid) >> 5;
    int nw = (gridDim.x * blockDim.x) >> 5;
    int chunk = (NE + nw - 1) / nw;
    int e0 = gw * chunk, e1 = min(NE, e0 + chunk);
    const unsigned* PQw = reinterpret_cast<const unsigned*>(g_PQ);  // 128 uints/row
    float2 sp = {0.f, 0.f}, qp = {0.f, 0.f}, sc = {0.f, 0.f}, qc = {0.f, 0.f};

    int e = e0;
    for (; e + 8 <= e1; e += 8) {
        int2 ep[8], ec[8];
#pragma unroll
        for (int u = 0; u < 8; u++) { ep[u] = g_eP[e + u]; ec[u] = g_eC[e + u]; }
        float2 pP[8], pQ[8], cP[8], cQ[8];
#pragma unroll
        for (int u = 0; u < 8; u++) {
            pP[u] = upk(PQw[ep[u].x * 128 + lane]);
            pQ[u] = upk(PQw[ep[u].y * 128 + 32 + lane]);
            cP[u] = upk(PQw[ec[u].x * 128 + 64 + lane]);
            cQ[u] = upk(PQw[ec[u].y * 128 + 96 + lane]);
        }
#pragma unroll
        for (int u = 0; u < 8; u++) {
            float2 v;
            v.x = pP[u].x + pQ[u].x; v.y = pP[u].y + pQ[u].y;
            sp.x += v.x; sp.y += v.y; qp.x += v.x * v.x; qp.y += v.y * v.y;
            v.x = cP[u].x + cQ[u].x; v.y = cP[u].y + cQ[u].y;
            sc.x += v.x; sc.y += v.y; qc.x += v.x * v.x; qc.y += v.y * v.y;
        }
    }
    for (; e < e1; e++) {
        int2 ep = g_eP[e], ec = g_eC[e];
        float2 pP = upk(PQw[ep.x * 128 + lane]);
        float2 pQ = upk(PQw[ep.y * 128 + 32 + lane]);
        float2 cP = upk(PQw[ec.x * 128 + 64 + lane]);
        float2 cQ = upk(PQw[ec.y * 128 + 96 + lane]);
        float2 v;
        v.x = pP.x + pQ.x; v.y = pP.y + pQ.y;
        sp.x += v.x; sp.y += v.y; qp.x += v.x * v.x; qp.y += v.y * v.y;
        v.x = cP.x + cQ.x; v.y = cP.y + cQ.y;
        sc.x += v.x; sc.y += v.y; qc.x += v.x * v.x; qc.y += v.y * v.y;
    }
    atomicAdd(&red[2 * lane],           sp.x); atomicAdd(&red[2 * lane + 1],       sp.y);
    atomicAdd(&red[64 + 2 * lane],      sc.x); atomicAdd(&red[64 + 2 * lane + 1],  sc.y);
    atomicAdd(&red[128 + 2 * lane],     qp.x); atomicAdd(&red[128 + 2 * lane + 1], qp.y);
    atomicAdd(&red[192 + 2 * lane],     qc.x); atomicAdd(&red[192 + 2 * lane + 1], qc.y);
    __syncthreads();
    if (tid < 256) atomicAdd(&g_stats[tid], red[tid]);
}

// ---------------- finalize BN1 ----------------
__global__ void k_fin1(const float* __restrict__ pg1, const float* __restrict__ pbe1,
                       const float* __restrict__ cg1, const float* __restrict__ cbe1) {
    int t = threadIdx.x;  // 128
    const float invE = 1.f / NE;
    if (t < 64) {
        float s = g_stats[t], q = g_stats[128 + t];
        float mu = s * invE;
        float rs = rsqrtf(q * invE - mu * mu + EPS);
        float A = pg1[t] * rs;
        g_stats[256 + t] = A;
        g_stats[384 + t] = pbe1[t] - A * mu;
        g_stats[t] = 0.f; g_stats[128 + t] = 0.f;
    } else {
        int c = t - 64;
        float s = g_stats[64 + c], q = g_stats[192 + c];
        float mu = s * invE;
        float rs = rsqrtf(q * invE - mu * mu + EPS);
        float A = cg1[c] * rs;
        g_stats[320 + c] = A;
        g_stats[448 + c] = cbe1[c] - A * mu;
        g_stats[64 + c] = 0.f; g_stats[192 + c] = 0.f;
    }
}

// ---------------- edge MLP both directions: 2 tiles of 128 edges per block ----------------
__global__ void k_edge2_dual() {
    extern __shared__ char smraw[];
    __half* h1h = reinterpret_cast<__half*>(smraw);                  // 128*72 halfs
    uint2*  Bf  = reinterpret_cast<uint2*>(smraw + 18432);           // 2048
    float*  prm = reinterpret_cast<float*>(smraw + 18432 + 16384);   // 256
    float*  sSt = prm + 256;                                         // 256
    int*    sIdx = reinterpret_cast<int*>(sSt + 256);                // 512

    int tid = threadIdx.x;
    int lane = tid & 31;
    int wid = tid >> 5;

    if (tid < 64) {
        prm[tid]       = g_stats[256 + tid];  // A1p
        prm[64 + tid]  = g_stats[384 + tid];  // D1p
        prm[128 + tid] = g_stats[320 + tid];  // A1c
        prm[192 + tid] = g_stats[448 + tid];  // D1c
    }
    sSt[tid] = 0.f;
    {
        const uint4* Bg = reinterpret_cast<const uint4*>(g_Bf);
        uint4* Bs4 = reinterpret_cast<uint4*>(Bf);
#pragma unroll
        for (int t = tid; t < 1024; t += 256) Bs4[t] = Bg[t];
    }

    const uint4* PQ4 = reinterpret_cast<const uint4*>(g_PQ);  // 32 uint4/row
    int m0 = wid * 16;
    int lr = (lane & 7) + ((lane >> 3) & 1) * 8;
    int lc = (lane >> 4) * 8;

    for (int tile = 0; tile < 2; tile++) {
        int e0 = blockIdx.x * 256 + tile * 128;
        // safe to (re)write sIdx: first tile had sync before use; later tiles pass
        // the dir-loop-end __syncthreads() before arriving here.
        if (tid < 128) {
            int2 ep = g_eP[e0 + tid];
            int2 ec = g_eC[e0 + tid];
            sIdx[tid]       = ep.x;
            sIdx[128 + tid] = ep.y;
            sIdx[256 + tid] = ec.x;
            sIdx[384 + tid] = ec.y;
        }
        __syncthreads();
        int row0 = e0 + m0 + (lane >> 2);

        for (int dir = 0; dir < 2; dir++) {
            int ib = dir * 256;
            int pbase = dir * 16;
            int pb = dir * 128;
            for (int t = tid; t < 1024; t += 256) {
                int er = t >> 3, q = t & 7;
                int i = sIdx[ib + er], j = sIdx[ib + 128 + er];
                uint4 pu = PQ4[i * 32 + pbase + q];
                uint4 qu = PQ4[j * 32 + pbase + 8 + q];
                float2 p0 = upk(pu.x), p1 = upk(pu.y), p2 = upk(pu.z), p3 = upk(pu.w);
                float2 r0 = upk(qu.x), r1 = upk(qu.y), r2 = upk(qu.z), r3 = upk(qu.w);
                int c = q * 8;
                float h0 = fmaxf(fmaf(prm[pb + c + 0], p0.x + r0.x, prm[pb + 64 + c + 0]), 0.f);
                float h1 = fmaxf(fmaf(prm[pb + c + 1], p0.y + r0.y, prm[pb + 64 + c + 1]), 0.f);
                float h2 = fmaxf(fmaf(prm[pb + c + 2], p1.x + r1.x, prm[pb + 64 + c + 2]), 0.f);
                float h3 = fmaxf(fmaf(prm[pb + c + 3], p1.y + r1.y, prm[pb + 64 + c + 3]), 0.f);
                float h4 = fmaxf(fmaf(prm[pb + c + 4], p2.x + r2.x, prm[pb + 64 + c + 4]), 0.f);
                float h5 = fmaxf(fmaf(prm[pb + c + 5], p2.y + r2.y, prm[pb + 64 + c + 5]), 0.f);
                float h6 = fmaxf(fmaf(prm[pb + c + 6], p3.x + r3.x, prm[pb + 64 + c + 6]), 0.f);
                float h7 = fmaxf(fmaf(prm[pb + c + 7], p3.y + r3.y, prm[pb + 64 + c + 7]), 0.f);
                uint4 o;
                o.x = pack_h2(h0, h1); o.y = pack_h2(h2, h3);
                o.z = pack_h2(h4, h5); o.w = pack_h2(h6, h7);
                *reinterpret_cast<uint4*>(&h1h[er * 72 + c]) = o;
            }
            __syncthreads();

            unsigned a[4][4];
#pragma unroll
            for (int kk = 0; kk < 4; kk++) {
                unsigned addr = (unsigned)__cvta_generic_to_shared(
                    &h1h[(m0 + lr) * 72 + kk * 16 + lc]);
                asm volatile("ldmatrix.sync.aligned.m8n8.x4.shared.b16 {%0,%1,%2,%3}, [%4];"
                             : "=r"(a[kk][0]), "=r"(a[kk][1]), "=r"(a[kk][2]), "=r"(a[kk][3])
                             : "r"(addr));
            }
            float acc[8][4];
#pragma unroll
            for (int nt = 0; nt < 8; nt++)
#pragma unroll
                for (int u = 0; u < 4; u++) acc[nt][u] = 0.f;

            int bbase = dir * 1024;
#pragma unroll
            for (int kk = 0; kk < 4; kk++) {
#pragma unroll
                for (int nt = 0; nt < 8; nt++) {
                    uint2 b = Bf[bbase + (kk * 8 + nt) * 32 + lane];
                    mma_f16(acc[nt], a[kk], b.x, b.y);
                }
            }

            __half* z2 = dir ? g_z2c : g_z2p;
            int sbase = dir * 128;
#pragma unroll
            for (int nt = 0; nt < 8; nt++) {
                int col = nt * 8 + (lane & 3) * 2;
                __half2 hv0 = __floats2half2_rn(acc[nt][0], acc[nt][1]);
                __half2 hv1 = __floats2half2_rn(acc[nt][2], acc[nt][3]);
                *reinterpret_cast<__half2*>(&z2[row0 * 64 + col])       = hv0;
                *reinterpret_cast<__half2*>(&z2[(row0 + 8) * 64 + col]) = hv1;
                float2 r0 = __half22float2(hv0), r1 = __half22float2(hv1);
                float se = r0.x + r1.x, qe = r0.x * r0.x + r1.x * r1.x;
                float so = r0.y + r1.y, qo = r0.y * r0.y + r1.y * r1.y;
#pragma unroll
                for (int off = 4; off < 32; off <<= 1) {
                    se += __shfl_xor_sync(0xffffffff, se, off);
                    qe += __shfl_xor_sync(0xffffffff, qe, off);
                    so += __shfl_xor_sync(0xffffffff, so, off);
                    qo += __shfl_xor_sync(0xffffffff, qo, off);
                }
                if (lane < 4) {
                    atomicAdd(&sSt[sbase + col], se);
                    atomicAdd(&sSt[sbase + 64 + col], qe);
                    atomicAdd(&sSt[sbase + col + 1], so);
                    atomicAdd(&sSt[sbase + 64 + col + 1], qo);
                }
            }
            __syncthreads();
        }
    }

    int dstoff;
    if (tid < 64)       dstoff = 512 + tid;
    else if (tid < 128) dstoff = 640 + (tid - 64);
    else if (tid < 192) dstoff = 576 + (tid - 128);
    else                dstoff = 704 + (tid - 192);
    atomicAdd(&g_stats[dstoff], sSt[tid]);
}

// ---------------- finalize BN2 ----------------
__global__ void k_fin2(const float* __restrict__ pg2, const float* __restrict__ pbe2,
                       const float* __restrict__ cg2, const float* __restrict__ cbe2) {
    int t = threadIdx.x;  // 128
    const float invE = 1.f / NE;
    if (t < 64) {
        float s = g_stats[512 + t], q = g_stats[640 + t];
        float mu = s * invE;
        float rs = rsqrtf(q * invE - mu * mu + EPS);
        float A = pg2[t] * rs;
        g_stats[768 + t] = A;
        g_stats[896 + t] = pbe2[t] - A * mu;
        g_stats[512 + t] = 0.f; g_stats[640 + t] = 0.f;
    } else {
        int c = t - 64;
        float s = g_stats[576 + c], q = g_stats[704 + c];
        float mu = s * invE;
        float rs = rsqrtf(q * invE - mu * mu + EPS);
        float A = cg2[c] * rs;
        g_stats[832 + c] = A;
        g_stats[960 + c] = cbe2[c] - A * mu;
        g_stats[576 + c] = 0.f; g_stats[704 + c] = 0.f;
    }
}

// ---------------- streaming aggregation: one warp per node, 8-row unroll, split by dir -----
__global__ void __launch_bounds__(256) k_gagg() {
    int lane = threadIdx.x & 31;
    int n = blockIdx.x * 8 + (threadIdx.x >> 5);
    if (blockIdx.y == 0) {
        float2 A = *reinterpret_cast<const float2*>(&g_stats[768 + 2 * lane]);
        float2 D = *reinterpret_cast<const float2*>(&g_stats[896 + 2 * lane]);
        int s = g_offP[n], t = g_offP[n + 1];
        float ax = 0.f, ay = 0.f;
        int k = s;
        for (; k + 8 <= t; k += 8) {
            float2 f[8];
#pragma unroll
            for (int u = 0; u < 8; u++)
                f[u] = upk(*reinterpret_cast<const unsigned*>(&g_z2p[(k + u) * 64 + lane * 2]));
#pragma unroll
            for (int u = 0; u < 8; u++) {
                ax += fmaxf(fmaf(A.x, f[u].x, D.x), 0.f);
                ay += fmaxf(fmaf(A.y, f[u].y, D.y), 0.f);
            }
        }
        for (; k < t; k++) {
            float2 f0 = upk(*reinterpret_cast<const unsigned*>(&g_z2p[k * 64 + lane * 2]));
            ax += fmaxf(fmaf(A.x, f0.x, D.x), 0.f);
            ay += fmaxf(fmaf(A.y, f0.y, D.y), 0.f);
        }
        float di = g_dinvP[n];
        *reinterpret_cast<float2*>(&g_aggP[n * 64 + lane * 2]) = make_float2(ax * di, ay * di);
    } else {
        float2 A = *reinterpret_cast<const float2*>(&g_stats[832 + 2 * lane]);
        float2 D = *reinterpret_cast<const float2*>(&g_stats[960 + 2 * lane]);
        int s = g_offC[n], t = g_offC[n + 1];
        float ax = 0.f, ay = 0.f;
        int k = s;
        for (; k + 8 <= t; k += 8) {
            float2 f[8];
#pragma unroll
            for (int u = 0; u < 8; u++)
                f[u] = upk(*reinterpret_cast<const unsigned*>(&g_z2c[(k + u) * 64 + lane * 2]));
#pragma unroll
            for (int u = 0; u < 8; u++) {
                ax += fmaxf(fmaf(A.x, f[u].x, D.x), 0.f);
                ay += fmaxf(fmaf(A.y, f[u].y, D.y), 0.f);
            }
        }
        for (; k < t; k++) {
            float2 f0 = upk(*reinterpret_cast<const unsigned*>(&g_z2c[k * 64 + lane * 2]));
            ax += fmaxf(fmaf(A.x, f0.x, D.x), 0.f);
            ay += fmaxf(fmaf(A.y, f0.y, D.y), 0.f);
        }
        float di = g_dinvC[n];
        *reinterpret_cast<float2*>(&g_aggC[n * 64 + lane * 2]) = make_float2(ax * di, ay * di);
    }
}

// ---------------- fused node update + next-iter PQ ----------------
__global__ void k_node12(const float* __restrict__ fcW, const float* __restrict__ fcb,
                         const float* __restrict__ fc2W, const float* __restrict__ fc2b,
                         const float* __restrict__ pW1, const float* __restrict__ cW1,
                         int do_pq) {
    extern __shared__ float sm[];
    float* As   = sm;            // [64][68]
    float* Bs   = sm + 4352;     // [64][64]
    float* tmpS = sm;            // aliases As+Bs, [64][130]
    float* Bs2  = sm + 8448;     // [64][64]

    int tid = threadIdx.x, tx = tid & 15, ty = tid >> 4;
    int nb = blockIdx.x * 64;

    float acc8[4][8] = {};
    for (int kc = 0; kc < 3; kc++) {
        __syncthreads();
        for (int t = tid; t < 1024; t += 256) {
            int r = t >> 4, q = t & 15;
            int row = nb + r;
            float4 v = make_float4(0.f, 0.f, 0.f, 0.f);
            if (row < NN) {
                if (kc == 0)      v = reinterpret_cast<const float4*>(g_x)[row * 16 + q];
                else if (kc == 1) v = reinterpret_cast<const float4*>(g_aggP)[row * 16 + q];
                else              v = reinterpret_cast<const float4*>(g_aggC)[row * 16 + q];
            }
            As[r * 68 + q * 4 + 0] = v.x; As[r * 68 + q * 4 + 1] = v.y;
            As[r * 68 + q * 4 + 2] = v.z; As[r * 68 + q * 4 + 3] = v.w;
        }
        for (int cc = 0; cc < 2; cc++) {
            __syncthreads();
            for (int t = tid; t < 4096; t += 256) {
                int k = t >> 6, c = t & 63;
                Bs[k * 64 + c] = fcW[(kc * 64 + k) * 128 + cc * 64 + c];
            }
            __syncthreads();
#pragma unroll 8
            for (int k = 0; k < 64; k++) {
                float a[4];
#pragma unroll
                for (int r = 0; r < 4; r++) a[r] = As[(ty * 4 + r) * 68 + k];
                float4 b = *reinterpret_cast<float4*>(&Bs[k * 64 + tx * 4]);
#pragma unroll
                for (int r = 0; r < 4; r++) {
                    acc8[r][cc * 4 + 0] += a[r] * b.x; acc8[r][cc * 4 + 1] += a[r] * b.y;
                    acc8[r][cc * 4 + 2] += a[r] * b.z; acc8[r][cc * 4 + 3] += a[r] * b.w;
                }
            }
        }
    }
    __syncthreads();
#pragma unroll
    for (int r = 0; r < 4; r++) {
#pragma unroll
        for (int cc = 0; cc < 2; cc++) {
            int c0 = cc * 64 + tx * 4;
#pragma unroll
            for (int u = 0; u < 4; u++)
                tmpS[(ty * 4 + r) * 130 + c0 + u] =
                    fmaxf(acc8[r][cc * 4 + u] + fcb[c0 + u], 0.f);
        }
    }

    float acc2[4][4] = {};
    for (int kc = 0; kc < 2; kc++) {
        __syncthreads();
        for (int t = tid; t < 4096; t += 256) {
            int k = t >> 6, c = t & 63;
            Bs2[k * 64 + c] = fc2W[(kc * 64 + k) * 64 + c];
        }
        __syncthreads();
#pragma unroll 8
        for (int k = 0; k < 64; k++) {
            float a[4];
#pragma unroll
            for (int r = 0; r < 4; r++) a[r] = tmpS[(ty * 4 + r) * 130 + kc * 64 + k];
            float4 b = *reinterpret_cast<float4*>(&Bs2[k * 64 + tx * 4]);
#pragma unroll
            for (int r = 0; r < 4; r++) {
                acc2[r][0] += a[r] * b.x; acc2[r][1] += a[r] * b.y;
                acc2[r][2] += a[r] * b.z; acc2[r][3] += a[r] * b.w;
            }
        }
    }
    __syncthreads();

#pragma unroll
    for (int r = 0; r < 4; r++) {
        int row = nb + ty * 4 + r;
        float4 nx = make_float4(0.f, 0.f, 0.f, 0.f);
        if (row < NN) {
            float4 x0 = reinterpret_cast<float4*>(g_x)[row * 16 + tx];
            nx.x = x0.x + acc2[r][0] + fc2b[tx * 4 + 0];
            nx.y = x0.y + acc2[r][1] + fc2b[tx * 4 + 1];
            nx.z = x0.z + acc2[r][2] + fc2b[tx * 4 + 2];
            nx.w = x0.w + acc2[r][3] + fc2b[tx * 4 + 3];
            reinterpret_cast<float4*>(g_x)[row * 16 + tx] = nx;
        }
        As[(ty * 4 + r) * 68 + tx * 4 + 0] = nx.x;
        As[(ty * 4 + r) * 68 + tx * 4 + 1] = nx.y;
        As[(ty * 4 + r) * 68 + tx * 4 + 2] = nx.z;
        As[(ty * 4 + r) * 68 + tx * 4 + 3] = nx.w;
    }
    if (!do_pq) return;

    for (int cc = 0; cc < 4; cc++) {
        __syncthreads();
        const float* W = (cc < 2) ? pW1 : cW1;
        int koff = (cc & 1) ? 64 : 0;
        for (int t = tid; t < 4096; t += 256) {
            int k = t >> 6, c = t & 63;
            Bs2[k * 64 + c] = W[(koff + k) * 64 + c];
        }
        __syncthreads();
        float acc[4][4] = {};
#pragma unroll 8
        for (int k = 0; k < 64; k++) {
            float a[4];
#pragma unroll
            for (int r = 0; r < 4; r++) a[r] = As[(ty * 4 + r) * 68 + k];
            float4 b = *reinterpret_cast<float4*>(&Bs2[k * 64 + tx * 4]);
#pragma unroll
            for (int r = 0; r < 4; r++) {
                acc[r][0] += a[r] * b.x; acc[r][1] += a[r] * b.y;
                acc[r][2] += a[r] * b.z; acc[r][3] += a[r] * b.w;
            }
        }
#pragma unroll
        for (int r = 0; r < 4; r++) {
            int row = nb + ty * 4 + r;
            if (row < NN) {
                uint2 o;
                o.x = pack_h2(acc[r][0], acc[r][1]);
                o.y = pack_h2(acc[r][2], acc[r][3]);
                reinterpret_cast<uint2*>(g_PQ)[row * 64 + cc * 16 + tx] = o;
            }
        }
    }
}

// ---------------- out = x @ convW + convb ----------------
__global__ void k_out(const float* __restrict__ convW, const float* __restrict__ convb,
                      float* __restrict__ out) {
    __shared__ float As[64][68];
    __shared__ float Bs[64][64];
    int tid = threadIdx.x, tx = tid & 15, ty = tid >> 4;
    int nb = blockIdx.x * 64;

    for (int t = tid; t < 1024; t += 256) {
        int r = t >> 4, q = t & 15;
        float4 v = make_float4(0.f, 0.f, 0.f, 0.f);
        if (nb + r < NN) v = reinterpret_cast<const float4*>(g_x)[(nb + r) * 16 + q];
        As[r][q * 4 + 0] = v.x; As[r][q * 4 + 1] = v.y;
        As[r][q * 4 + 2] = v.z; As[r][q * 4 + 3] = v.w;
    }
    for (int cc = 0; cc < 2; cc++) {
        __syncthreads();
        for (int t = tid; t < 4096; t += 256) {
            int k = t >> 6, c = t & 63;
            Bs[k][c] = convW[k * 128 + cc * 64 + c];
        }
        __syncthreads();
        float acc[4][4] = {};
#pragma unroll 8
        for (int k = 0; k < 64; k++) {
            float a[4];
#pragma unroll
            for (int r = 0; r < 4; r++) a[r] = As[ty * 4 + r][k];
            float4 b = *reinterpret_cast<float4*>(&Bs[k][tx * 4]);
#pragma unroll
            for (int r = 0; r < 4; r++) {
                acc[r][0] += a[r] * b.x; acc[r][1] += a[r] * b.y;
                acc[r][2] += a[r] * b.z; acc[r][3] += a[r] * b.w;
            }
        }
#pragma unroll
        for (int r = 0; r < 4; r++) {
            int row = nb + ty * 4 + r;
            if (row < NN) {
                float4 o;
                o.x = acc[r][0] + convb[cc * 64 + tx * 4 + 0];
                o.y = acc[r][1] + convb[cc * 64 + tx * 4 + 1];
                o.z = acc[r][2] + convb[cc * 64 + tx * 4 + 2];
                o.w = acc[r][3] + convb[cc * 64 + tx * 4 + 3];
                reinterpret_cast<float4*>(out)[row * 32 + cc * 16 + tx] = o;
            }
        }
    }
}

// ---------------- host launcher ----------------
extern "C" void kernel_launch(void* const* d_in, const int* in_sizes, int n_in,
                              void* d_out, int out_size) {
    (void)in_sizes; (void)n_in; (void)out_size;
    const int*   nodes = (const int*)d_in[0];
    const int*   edges = (const int*)d_in[1];
    const int*   src   = edges;            // edges[0]
    const int*   dst   = edges + NE;       // edges[1]
    const float* emb   = (const float*)d_in[2];
    const float* pW1 = (const float*)d_in[3];
    const float* pg1 = (const float*)d_in[5],  *pbe1 = (const float*)d_in[6];
    const float* pW2 = (const float*)d_in[7];
    const float* pg2 = (const float*)d_in[9],  *pbe2 = (const float*)d_in[10];
    const float* cW1 = (const float*)d_in[11];
    const float* cg1 = (const float*)d_in[13], *cbe1 = (const float*)d_in[14];
    const float* cW2 = (const float*)d_in[15];
    const float* cg2 = (const float*)d_in[17], *cbe2 = (const float*)d_in[18];
    const float* fcW  = (const float*)d_in[19], *fcb  = (const float*)d_in[20];
    const float* fc2W = (const float*)d_in[21], *fc2b = (const float*)d_in[22];
    const float* convW = (const float*)d_in[23], *convb = (const float*)d_in[24];
    float* out = (float*)d_out;

    const int EDGE2_SMEM = 18432 + 16384 + 256 * 4 + 256 * 4 + 512 * 4;  // 38912
    const int NODE12_SMEM = (8448 + 4096) * 4;                           // 50176
    cudaFuncSetAttribute(k_edge2_dual, cudaFuncAttributeMaxDynamicSharedMemorySize, EDGE2_SMEM);
    cudaFuncSetAttribute(k_node12, cudaFuncAttributeMaxDynamicSharedMemorySize, NODE12_SMEM);

    k_zero<<<196, 256>>>();
    k_init<<<6258, 256>>>(nodes, emb, src, dst, pW2, cW2);
    {
        dim3 g(NBLK, 2);
        k_scanA<<<g, 1024>>>();
        k_scanB<<<1, 128>>>();
        k_scanC<<<g, 1024>>>();
    }
    k_fill<<<3125, 256>>>(src, dst);
    k_pq_dual<<<782, 256>>>(pW1, cW1);

    for (int it = 0; it < 2; it++) {
        k_stats1_dual<<<592, 512>>>();
        k_fin1<<<1, 128>>>(pg1, pbe1, cg1, cbe1);
        k_edge2_dual<<<3125, 256, EDGE2_SMEM>>>();
        k_fin2<<<1, 128>>>(pg2, pbe2, cg2, cbe2);
        {
            dim3 gg(6250, 2);
            k_gagg<<<gg, 256>>>();
        }
        k_node12<<<782, 256, NODE12_SMEM>>>(fcW, fcb, fc2W, fc2b, pW1, cW1, it == 0);
    }
    k_out<<<782, 256>>>(convW, convb, out);
}

// round 14
// speedup vs baseline: 1.0217x; 1.0217x over previous
#include <cuda_runtime.h>
#include <cuda_fp16.h>

#define NN 50000
#define NE 800000
#define EPS 1e-5f
#define NBLK 49   // ceil(NN/1024)

// ---------------- static scratch ----------------
__device__ __align__(16) float  g_x[NN * 64];       // node features
__device__ __align__(16) __half g_PQ[NN * 256];     // per-node [pP|pQ|cP|cQ] fp16
__device__ __align__(16) __half g_z2p[NE * 64];     // parent z2 (fp16), CSR(dst) order
__device__ __align__(16) __half g_z2c[NE * 64];     // child z2 (fp16), CSR(src) order
__device__ __align__(16) float  g_aggP[NN * 64];    // deg-normalized parent agg
__device__ __align__(16) float  g_aggC[NN * 64];
__device__ int   g_cntP[NN], g_cntC[NN];            // degree counts, then fill cursors
__device__ int   g_offP[NN + 1], g_offC[NN + 1];    // CSR offsets
__device__ __align__(8) int2 g_eP[NE];              // parent-dir (i=dst, j=src), sorted by i
__device__ __align__(8) int2 g_eC[NE];              // child-dir (i=src, j=dst), sorted by i
__device__ float g_dinvP[NN], g_dinvC[NN];
__device__ __align__(16) uint2 g_Bf[2048];          // pre-packed W2 MMA fragments (p|c)
__device__ int   g_bsum[2 * NBLK];                  // scan block sums
// [0:64]S1p [64:128]S1c [128:192]Q1p [192:256]Q1c
// [256:320]A1p [320:384]A1c [384:448]D1p [448:512]D1c
// [512:576]S2p [576:640]S2c [640:704]Q2p [704:768]Q2c
// [768:832]A2p [832:896]A2c [896:960]D2p [960:1024]D2c
__device__ __align__(16) float g_stats[1024];

__device__ __forceinline__ unsigned pack_h2(float a, float b) {
    __half2 h = __floats2half2_rn(a, b);
    return *reinterpret_cast<unsigned*>(&h);
}
__device__ __forceinline__ float2 upk(unsigned u) {
    return __half22float2(*reinterpret_cast<__half2*>(&u));
}

__device__ __forceinline__ void mma_f16(float* c, const unsigned* a, unsigned b0, unsigned b1) {
    asm volatile(
        "mma.sync.aligned.m16n8k16.row.col.f32.f16.f16.f32 "
        "{%0,%1,%2,%3}, {%4,%5,%6,%7}, {%8,%9}, {%0,%1,%2,%3};"
        : "+f"(c[0]), "+f"(c[1]), "+f"(c[2]), "+f"(c[3])
        : "r"(a[0]), "r"(a[1]), "r"(a[2]), "r"(a[3]), "r"(b0), "r"(b1));
}

// ---------------- zero counters + stats ----------------
__global__ void k_zero() {
    int t = blockIdx.x * blockDim.x + threadIdx.x;
    if (t < NN) { g_cntP[t] = 0; g_cntC[t] = 0; }
    if (t < 1024) g_stats[t] = 0.f;
}

// ---------------- fused setup: embed || degree || pack ----------------
__global__ void k_init(const int* __restrict__ nodes, const float* __restrict__ emb,
                       const int* __restrict__ src, const int* __restrict__ dst,
                       const float* __restrict__ pW2, const float* __restrict__ cW2) {
    int b = blockIdx.x;
    int tid = threadIdx.x;
    if (b < 3125) {
        int t = b * 256 + tid;
        int n = t >> 4, q = t & 15;
        reinterpret_cast<float4*>(g_x)[t] =
            reinterpret_cast<const float4*>(emb)[nodes[n] * 16 + q];
    } else if (b < 6250) {
        int e = (b - 3125) * 256 + tid;
        atomicAdd(&g_cntP[dst[e]], 1);
        atomicAdd(&g_cntC[src[e]], 1);
    } else {
        int t = (b - 6250) * 256 + tid;
        if (t < 2048) {
            int dir = t >> 10, u = t & 1023;
            int kk = u >> 8, nt = (u >> 5) & 7, ln = u & 31;
            int k0 = kk * 16 + (ln & 3) * 2;
            int n  = nt * 8 + (ln >> 2);
            const float* W = dir ? cW2 : pW2;
            uint2 v;
            v.x = pack_h2(W[k0 * 64 + n],       W[(k0 + 1) * 64 + n]);
            v.y = pack_h2(W[(k0 + 8) * 64 + n], W[(k0 + 9) * 64 + n]);
            g_Bf[t] = v;
        }
    }
}

// ---------------- parallel scan phase A: per-chunk block sums ----------------
__global__ void k_scanA() {
    __shared__ int ws[32];
    int half = blockIdx.y;
    int idx = blockIdx.x * 1024 + threadIdx.x;
    int lane = threadIdx.x & 31, w = threadIdx.x >> 5;
    const int* cnt = half ? g_cntC : g_cntP;
    int v = (idx < NN) ? cnt[idx] : 0;
#pragma unroll
    for (int o = 16; o > 0; o >>= 1) v += __shfl_down_sync(0xffffffff, v, o);
    if (lane == 0) ws[w] = v;
    __syncthreads();
    if (threadIdx.x < 32) {
        int s = ws[threadIdx.x];
#pragma unroll
        for (int o = 16; o > 0; o >>= 1) s += __shfl_down_sync(0xffffffff, s, o);
        if (threadIdx.x == 0) g_bsum[half * NBLK + blockIdx.x] = s;
    }
}

// ---------------- parallel scan phase B: 64-wide Hillis-Steele over block sums ----------------
__global__ void k_scanB() {
    __shared__ int sh[2][64];
    int t = threadIdx.x;           // 128 threads
    int half = t >> 6, i = t & 63;
    int v = (i < NBLK) ? g_bsum[half * NBLK + i] : 0;
    sh[half][i] = v;
    __syncthreads();
#pragma unroll
    for (int o = 1; o < 64; o <<= 1) {
        int add = (i >= o) ? sh[half][i - o] : 0;
        __syncthreads();
        sh[half][i] += add;
        __syncthreads();
    }
    if (i < NBLK) g_bsum[half * NBLK + i] = sh[half][i] - v;  // exclusive
    if (i == NBLK - 1) (half ? g_offC : g_offP)[NN] = sh[half][NBLK - 1];
}

// ---------------- parallel scan phase C: per-chunk scan + base; dinv; zero cursors ----------------
__global__ void k_scanC() {
    __shared__ int wsum[32];
    int half = blockIdx.y;
    int idx = blockIdx.x * 1024 + threadIdx.x;
    int lane = threadIdx.x & 31, w = threadIdx.x >> 5;
    int* cnt = half ? g_cntC : g_cntP;
    int* off = half ? g_offC : g_offP;
    float* dinv = half ? g_dinvC : g_dinvP;
    int v = (idx < NN) ? cnt[idx] : 0;
    int x = v;
#pragma unroll
    for (int o = 1; o < 32; o <<= 1) {
        int y = __shfl_up_sync(0xffffffff, x, o);
        if (lane >= o) x += y;
    }
    if (lane == 31) wsum[w] = x;
    __syncthreads();
    if (w == 0) {
        int s = wsum[lane];
#pragma unroll
        for (int o = 1; o < 32; o <<= 1) {
            int y = __shfl_up_sync(0xffffffff, s, o);
            if (lane >= o) s += y;
        }
        wsum[lane] = s;
    }
    __syncthreads();
    int incl = x + (w ? wsum[w - 1] : 0);
    int excl = incl - v + g_bsum[half * NBLK + blockIdx.x];
    if (idx < NN) {
        off[idx] = excl;
        dinv[idx] = v ? (1.f / v) : 0.f;
        cnt[idx] = 0;
    }
}

// fill direction-sorted edge lists (packed int2)
__global__ void k_fill(const int* __restrict__ src, const int* __restrict__ dst) {
    int e = blockIdx.x * blockDim.x + threadIdx.x;
    if (e < NE) {
        int s = src[e], d = dst[e];
        int p = atomicAdd(&g_cntP[d], 1);
        g_eP[g_offP[d] + p] = make_int2(d, s);
        int c = atomicAdd(&g_cntC[s], 1);
        g_eC[g_offC[s] + c] = make_int2(s, d);
    }
}

// ---------------- PQ = x @ [pW1t|pW1b|cW1t|cW1b]  (first iteration only) ----------------
__global__ void k_pq_dual(const float* __restrict__ pW1, const float* __restrict__ cW1) {
    __shared__ float As[64][68];
    __shared__ float Bs[64][64];
    int tid = threadIdx.x;
    int tx = tid & 15, ty = tid >> 4;
    int nb = blockIdx.x * 64;

    for (int t = tid; t < 1024; t += 256) {
        int r = t >> 4, q = t & 15;
        float4 v = make_float4(0.f, 0.f, 0.f, 0.f);
        if (nb + r < NN) v = reinterpret_cast<const float4*>(g_x)[(nb + r) * 16 + q];
        As[r][q * 4 + 0] = v.x; As[r][q * 4 + 1] = v.y;
        As[r][q * 4 + 2] = v.z; As[r][q * 4 + 3] = v.w;
    }
    for (int cc = 0; cc < 4; cc++) {
        __syncthreads();
        const float* W = (cc < 2) ? pW1 : cW1;
        int koff = (cc & 1) ? 64 : 0;
        for (int t = tid; t < 4096; t += 256) {
            int k = t >> 6, c = t & 63;
            Bs[k][c] = W[(koff + k) * 64 + c];
        }
        __syncthreads();
        float acc[4][4] = {};
#pragma unroll 8
        for (int k = 0; k < 64; k++) {
            float a[4];
#pragma unroll
            for (int r = 0; r < 4; r++) a[r] = As[ty * 4 + r][k];
            float4 b = *reinterpret_cast<float4*>(&Bs[k][tx * 4]);
#pragma unroll
            for (int r = 0; r < 4; r++) {
                acc[r][0] += a[r] * b.x; acc[r][1] += a[r] * b.y;
                acc[r][2] += a[r] * b.z; acc[r][3] += a[r] * b.w;
            }
        }
#pragma unroll
        for (int r = 0; r < 4; r++) {
            int row = nb + ty * 4 + r;
            if (row < NN) {
                uint2 o;
                o.x = pack_h2(acc[r][0], acc[r][1]);
                o.y = pack_h2(acc[r][2], acc[r][3]);
                reinterpret_cast<uint2*>(g_PQ)[row * 64 + cc * 16 + tx] = o;
            }
        }
    }
}

// ---------------- z1 stats, both directions, contiguous chunks, 4-edge unroll ----------------
__global__ void k_stats1_dual() {
    __shared__ float red[256];
    int tid = threadIdx.x;
    if (tid < 256) red[tid] = 0.f;
    __syncthreads();
    int lane = tid & 31;
    int gw = (blockIdx.x * blockDim.x + tid) >> 5;
    int nw = (gridDim.x * blockDim.x) >> 5;
    int chunk = (NE + nw - 1) / nw;
    int e0 = gw * chunk, e1 = min(NE, e0 + chunk);
    const unsigned* PQw = reinterpret_cast<const unsigned*>(g_PQ);  // 128 uints/row
    float2 sp = {0.f, 0.f}, qp = {0.f, 0.f}, sc = {0.f, 0.f}, qc = {0.f, 0.f};

    int e = e0;
    for (; e + 4 <= e1; e += 4) {
        int2 ep[4], ec[4];
#pragma unroll
        for (int u = 0; u < 4; u++) { ep[u] = g_eP[e + u]; ec[u] = g_eC[e + u]; }
        float2 pP[4], pQ[4], cP[4], cQ[4];
#pragma unroll
        for (int u = 0; u < 4; u++) {
            pP[u] = upk(PQw[ep[u].x * 128 + lane]);
            pQ[u] = upk(PQw[ep[u].y * 128 + 32 + lane]);
            cP[u] = upk(PQw[ec[u].x * 128 + 64 + lane]);
            cQ[u] = upk(PQw[ec[u].y * 128 + 96 + lane]);
        }
#pragma unroll
        for (int u = 0; u < 4; u++) {
            float2 v;
            v.x = pP[u].x + pQ[u].x; v.y = pP[u].y + pQ[u].y;
            sp.x += v.x; sp.y += v.y; qp.x += v.x * v.x; qp.y += v.y * v.y;
            v.x = cP[u].x + cQ[u].x; v.y = cP[u].y + cQ[u].y;
            sc.x += v.x; sc.y += v.y; qc.x += v.x * v.x; qc.y += v.y * v.y;
        }
    }
    for (; e < e1; e++) {
        int2 ep = g_eP[e], ec = g_eC[e];
        float2 pP = upk(PQw[ep.x * 128 + lane]);
        float2 pQ = upk(PQw[ep.y * 128 + 32 + lane]);
        float2 cP = upk(PQw[ec.x * 128 + 64 + lane]);
        float2 cQ = upk(PQw[ec.y * 128 + 96 + lane]);
        float2 v;
        v.x = pP.x + pQ.x; v.y = pP.y + pQ.y;
        sp.x += v.x; sp.y += v.y; qp.x += v.x * v.x; qp.y += v.y * v.y;
        v.x = cP.x + cQ.x; v.y = cP.y + cQ.y;
        sc.x += v.x; sc.y += v.y; qc.x += v.x * v.x; qc.y += v.y * v.y;
    }
    atomicAdd(&red[2 * lane],           sp.x); atomicAdd(&red[2 * lane + 1],       sp.y);
    atomicAdd(&red[64 + 2 * lane],      sc.x); atomicAdd(&red[64 + 2 * lane + 1],  sc.y);
    atomicAdd(&red[128 + 2 * lane],     qp.x); atomicAdd(&red[128 + 2 * lane + 1], qp.y);
    atomicAdd(&red[192 + 2 * lane],     qc.x); atomicAdd(&red[192 + 2 * lane + 1], qc.y);
    __syncthreads();
    if (tid < 256) atomicAdd(&g_stats[tid], red[tid]);
}

// ---------------- finalize BN1 ----------------
__global__ void k_fin1(const float* __restrict__ pg1, const float* __restrict__ pbe1,
                       const float* __restrict__ cg1, const float* __restrict__ cbe1) {
    int t = threadIdx.x;  // 128
    const float invE = 1.f / NE;
    if (t < 64) {
        float s = g_stats[t], q = g_stats[128 + t];
        float mu = s * invE;
        float rs = rsqrtf(q * invE - mu * mu + EPS);
        float A = pg1[t] * rs;
        g_stats[256 + t] = A;
        g_stats[384 + t] = pbe1[t] - A * mu;
        g_stats[t] = 0.f; g_stats[128 + t] = 0.f;
    } else {
        int c = t - 64;
        float s = g_stats[64 + c], q = g_stats[192 + c];
        float mu = s * invE;
        float rs = rsqrtf(q * invE - mu * mu + EPS);
        float A = cg1[c] * rs;
        g_stats[320 + c] = A;
        g_stats[448 + c] = cbe1[c] - A * mu;
        g_stats[64 + c] = 0.f; g_stats[192 + c] = 0.f;
    }
}

// ---------------- edge MLP both directions: BN1+ReLU -> fp16 MMA -> fp16 z2 + stats ----------
__global__ void k_edge2_dual() {
    extern __shared__ char smraw[];
    __half* h1h = reinterpret_cast<__half*>(smraw);                  // 128*72 halfs
    uint2*  Bf  = reinterpret_cast<uint2*>(smraw + 18432);           // 2048
    float*  prm = reinterpret_cast<float*>(smraw + 18432 + 16384);   // 256
    float*  sSt = prm + 256;                                         // 256
    int*    sIdx = reinterpret_cast<int*>(sSt + 256);                // 512

    int tid = threadIdx.x;
    int lane = tid & 31;
    int wid = tid >> 5;
    int e0 = blockIdx.x * 128;

    if (tid < 64) {
        prm[tid]       = g_stats[256 + tid];  // A1p
        prm[64 + tid]  = g_stats[384 + tid];  // D1p
        prm[128 + tid] = g_stats[320 + tid];  // A1c
        prm[192 + tid] = g_stats[448 + tid];  // D1c
    }
    sSt[tid] = 0.f;
    if (tid < 128) {
        int2 ep = g_eP[e0 + tid];
        int2 ec = g_eC[e0 + tid];
        sIdx[tid]       = ep.x;
        sIdx[128 + tid] = ep.y;
        sIdx[256 + tid] = ec.x;
        sIdx[384 + tid] = ec.y;
    }
    {
        const uint4* Bg = reinterpret_cast<const uint4*>(g_Bf);
        uint4* Bs4 = reinterpret_cast<uint4*>(Bf);
#pragma unroll
        for (int t = tid; t < 1024; t += 256) Bs4[t] = Bg[t];
    }
    __syncthreads();

    const uint4* PQ4 = reinterpret_cast<const uint4*>(g_PQ);  // 32 uint4/row
    int m0 = wid * 16;
    int lr = (lane & 7) + ((lane >> 3) & 1) * 8;
    int lc = (lane >> 4) * 8;
    int row0 = e0 + m0 + (lane >> 2);

    for (int dir = 0; dir < 2; dir++) {
        int ib = dir * 256;
        int pbase = dir * 16;
        int pb = dir * 128;
        for (int t = tid; t < 1024; t += 256) {
            int er = t >> 3, q = t & 7;
            int i = sIdx[ib + er], j = sIdx[ib + 128 + er];
            uint4 pu = PQ4[i * 32 + pbase + q];
            uint4 qu = PQ4[j * 32 + pbase + 8 + q];
            float2 p0 = upk(pu.x), p1 = upk(pu.y), p2 = upk(pu.z), p3 = upk(pu.w);
            float2 r0 = upk(qu.x), r1 = upk(qu.y), r2 = upk(qu.z), r3 = upk(qu.w);
            int c = q * 8;
            float h0 = fmaxf(fmaf(prm[pb + c + 0], p0.x + r0.x, prm[pb + 64 + c + 0]), 0.f);
            float h1 = fmaxf(fmaf(prm[pb + c + 1], p0.y + r0.y, prm[pb + 64 + c + 1]), 0.f);
            float h2 = fmaxf(fmaf(prm[pb + c + 2], p1.x + r1.x, prm[pb + 64 + c + 2]), 0.f);
            float h3 = fmaxf(fmaf(prm[pb + c + 3], p1.y + r1.y, prm[pb + 64 + c + 3]), 0.f);
            float h4 = fmaxf(fmaf(prm[pb + c + 4], p2.x + r2.x, prm[pb + 64 + c + 4]), 0.f);
            float h5 = fmaxf(fmaf(prm[pb + c + 5], p2.y + r2.y, prm[pb + 64 + c + 5]), 0.f);
            float h6 = fmaxf(fmaf(prm[pb + c + 6], p3.x + r3.x, prm[pb + 64 + c + 6]), 0.f);
            float h7 = fmaxf(fmaf(prm[pb + c + 7], p3.y + r3.y, prm[pb + 64 + c + 7]), 0.f);
            uint4 o;
            o.x = pack_h2(h0, h1); o.y = pack_h2(h2, h3);
            o.z = pack_h2(h4, h5); o.w = pack_h2(h6, h7);
            *reinterpret_cast<uint4*>(&h1h[er * 72 + c]) = o;
        }
        __syncthreads();

        unsigned a[4][4];
#pragma unroll
        for (int kk = 0; kk < 4; kk++) {
            unsigned addr = (unsigned)__cvta_generic_to_shared(
                &h1h[(m0 + lr) * 72 + kk * 16 + lc]);
            asm volatile("ldmatrix.sync.aligned.m8n8.x4.shared.b16 {%0,%1,%2,%3}, [%4];"
                         : "=r"(a[kk][0]), "=r"(a[kk][1]), "=r"(a[kk][2]), "=r"(a[kk][3])
                         : "r"(addr));
        }
        float acc[8][4];
#pragma unroll
        for (int nt = 0; nt < 8; nt++)
#pragma unroll
            for (int u = 0; u < 4; u++) acc[nt][u] = 0.f;

        int bbase = dir * 1024;
#pragma unroll
        for (int kk = 0; kk < 4; kk++) {
#pragma unroll
            for (int nt = 0; nt < 8; nt++) {
                uint2 b = Bf[bbase + (kk * 8 + nt) * 32 + lane];
                mma_f16(acc[nt], a[kk], b.x, b.y);
            }
        }

        __half* z2 = dir ? g_z2c : g_z2p;
        int sbase = dir * 128;
#pragma unroll
        for (int nt = 0; nt < 8; nt++) {
            int col = nt * 8 + (lane & 3) * 2;
            __half2 hv0 = __floats2half2_rn(acc[nt][0], acc[nt][1]);
            __half2 hv1 = __floats2half2_rn(acc[nt][2], acc[nt][3]);
            *reinterpret_cast<__half2*>(&z2[row0 * 64 + col])       = hv0;
            *reinterpret_cast<__half2*>(&z2[(row0 + 8) * 64 + col]) = hv1;
            float2 r0 = __half22float2(hv0), r1 = __half22float2(hv1);
            float se = r0.x + r1.x, qe = r0.x * r0.x + r1.x * r1.x;
            float so = r0.y + r1.y, qo = r0.y * r0.y + r1.y * r1.y;
#pragma unroll
            for (int off = 4; off < 32; off <<= 1) {
                se += __shfl_xor_sync(0xffffffff, se, off);
                qe += __shfl_xor_sync(0xffffffff, qe, off);
                so += __shfl_xor_sync(0xffffffff, so, off);
                qo += __shfl_xor_sync(0xffffffff, qo, off);
            }
            if (lane < 4) {
                atomicAdd(&sSt[sbase + col], se);
                atomicAdd(&sSt[sbase + 64 + col], qe);
                atomicAdd(&sSt[sbase + col + 1], so);
                atomicAdd(&sSt[sbase + 64 + col + 1], qo);
            }
        }
        __syncthreads();
    }

    int dstoff;
    if (tid < 64)       dstoff = 512 + tid;
    else if (tid < 128) dstoff = 640 + (tid - 64);
    else if (tid < 192) dstoff = 576 + (tid - 128);
    else                dstoff = 704 + (tid - 192);
    atomicAdd(&g_stats[dstoff], sSt[tid]);
}

// ---------------- finalize BN2 ----------------
__global__ void k_fin2(const float* __restrict__ pg2, const float* __restrict__ pbe2,
                       const float* __restrict__ cg2, const float* __restrict__ cbe2) {
    int t = threadIdx.x;  // 128
    const float invE = 1.f / NE;
    if (t < 64) {
        float s = g_stats[512 + t], q = g_stats[640 + t];
        float mu = s * invE;
        float rs = rsqrtf(q * invE - mu * mu + EPS);
        float A = pg2[t] * rs;
        g_stats[768 + t] = A;
        g_stats[896 + t] = pbe2[t] - A * mu;
        g_stats[512 + t] = 0.f; g_stats[640 + t] = 0.f;
    } else {
        int c = t - 64;
        float s = g_stats[576 + c], q = g_stats[704 + c];
        float mu = s * invE;
        float rs = rsqrtf(q * invE - mu * mu + EPS);
        float A = cg2[c] * rs;
        g_stats[832 + c] = A;
        g_stats[960 + c] = cbe2[c] - A * mu;
        g_stats[576 + c] = 0.f; g_stats[704 + c] = 0.f;
    }
}

// ---------------- streaming aggregation: one warp per node, 8-row unroll, split by dir -----
__global__ void __launch_bounds__(256) k_gagg() {
    int lane = threadIdx.x & 31;
    int n = blockIdx.x * 8 + (threadIdx.x >> 5);
    if (blockIdx.y == 0) {
        float2 A = *reinterpret_cast<const float2*>(&g_stats[768 + 2 * lane]);
        float2 D = *reinterpret_cast<const float2*>(&g_stats[896 + 2 * lane]);
        int s = g_offP[n], t = g_offP[n + 1];
        float ax = 0.f, ay = 0.f;
        int k = s;
        for (; k + 8 <= t; k += 8) {
            float2 f[8];
#pragma unroll
            for (int u = 0; u < 8; u++)
                f[u] = upk(*reinterpret_cast<const unsigned*>(&g_z2p[(k + u) * 64 + lane * 2]));
#pragma unroll
            for (int u = 0; u < 8; u++) {
                ax += fmaxf(fmaf(A.x, f[u].x, D.x), 0.f);
                ay += fmaxf(fmaf(A.y, f[u].y, D.y), 0.f);
            }
        }
        for (; k < t; k++) {
            float2 f0 = upk(*reinterpret_cast<const unsigned*>(&g_z2p[k * 64 + lane * 2]));
            ax += fmaxf(fmaf(A.x, f0.x, D.x), 0.f);
            ay += fmaxf(fmaf(A.y, f0.y, D.y), 0.f);
        }
        float di = g_dinvP[n];
        *reinterpret_cast<float2*>(&g_aggP[n * 64 + lane * 2]) = make_float2(ax * di, ay * di);
    } else {
        float2 A = *reinterpret_cast<const float2*>(&g_stats[832 + 2 * lane]);
        float2 D = *reinterpret_cast<const float2*>(&g_stats[960 + 2 * lane]);
        int s = g_offC[n], t = g_offC[n + 1];
        float ax = 0.f, ay = 0.f;
        int k = s;
        for (; k + 8 <= t; k += 8) {
            float2 f[8];
#pragma unroll
            for (int u = 0; u < 8; u++)
                f[u] = upk(*reinterpret_cast<const unsigned*>(&g_z2c[(k + u) * 64 + lane * 2]));
#pragma unroll
            for (int u = 0; u < 8; u++) {
                ax += fmaxf(fmaf(A.x, f[u].x, D.x), 0.f);
                ay += fmaxf(fmaf(A.y, f[u].y, D.y), 0.f);
            }
        }
        for (; k < t; k++) {
            float2 f0 = upk(*reinterpret_cast<const unsigned*>(&g_z2c[k * 64 + lane * 2]));
            ax += fmaxf(fmaf(A.x, f0.x, D.x), 0.f);
            ay += fmaxf(fmaf(A.y, f0.y, D.y), 0.f);
        }
        float di = g_dinvC[n];
        *reinterpret_cast<float2*>(&g_aggC[n * 64 + lane * 2]) = make_float2(ax * di, ay * di);
    }
}

// ---------------- fused node update + next-iter PQ ----------------
__global__ void k_node12(const float* __restrict__ fcW, const float* __restrict__ fcb,
                         const float* __restrict__ fc2W, const float* __restrict__ fc2b,
                         const float* __restrict__ pW1, const float* __restrict__ cW1,
                         int do_pq) {
    extern __shared__ float sm[];
    float* As   = sm;            // [64][68]
    float* Bs   = sm + 4352;     // [64][64]
    float* tmpS = sm;            // aliases As+Bs, [64][130]
    float* Bs2  = sm + 8448;     // [64][64]

    int tid = threadIdx.x, tx = tid & 15, ty = tid >> 4;
    int nb = blockIdx.x * 64;

    float acc8[4][8] = {};
    for (int kc = 0; kc < 3; kc++) {
        __syncthreads();
        for (int t = tid; t < 1024; t += 256) {
            int r = t >> 4, q = t & 15;
            int row = nb + r;
            float4 v = make_float4(0.f, 0.f, 0.f, 0.f);
            if (row < NN) {
                if (kc == 0)      v = reinterpret_cast<const float4*>(g_x)[row * 16 + q];
                else if (kc == 1) v = reinterpret_cast<const float4*>(g_aggP)[row * 16 + q];
                else              v = reinterpret_cast<const float4*>(g_aggC)[row * 16 + q];
            }
            As[r * 68 + q * 4 + 0] = v.x; As[r * 68 + q * 4 + 1] = v.y;
            As[r * 68 + q * 4 + 2] = v.z; As[r * 68 + q * 4 + 3] = v.w;
        }
        for (int cc = 0; cc < 2; cc++) {
            __syncthreads();
            for (int t = tid; t < 4096; t += 256) {
                int k = t >> 6, c = t & 63;
                Bs[k * 64 + c] = fcW[(kc * 64 + k) * 128 + cc * 64 + c];
            }
            __syncthreads();
#pragma unroll 8
            for (int k = 0; k < 64; k++) {
                float a[4];
#pragma unroll
                for (int r = 0; r < 4; r++) a[r] = As[(ty * 4 + r) * 68 + k];
                float4 b = *reinterpret_cast<float4*>(&Bs[k * 64 + tx * 4]);
#pragma unroll
                for (int r = 0; r < 4; r++) {
                    acc8[r][cc * 4 + 0] += a[r] * b.x; acc8[r][cc * 4 + 1] += a[r] * b.y;
                    acc8[r][cc * 4 + 2] += a[r] * b.z; acc8[r][cc * 4 + 3] += a[r] * b.w;
                }
            }
        }
    }
    __syncthreads();
#pragma unroll
    for (int r = 0; r < 4; r++) {
#pragma unroll
        for (int cc = 0; cc < 2; cc++) {
            int c0 = cc * 64 + tx * 4;
#pragma unroll
            for (int u = 0; u < 4; u++)
                tmpS[(ty * 4 + r) * 130 + c0 + u] =
                    fmaxf(acc8[r][cc * 4 + u] + fcb[c0 + u], 0.f);
        }
    }

    float acc2[4][4] = {};
    for (int kc = 0; kc < 2; kc++) {
        __syncthreads();
        for (int t = tid; t < 4096; t += 256) {
            int k = t >> 6, c = t & 63;
            Bs2[k * 64 + c] = fc2W[(kc * 64 + k) * 64 + c];
        }
        __syncthreads();
#pragma unroll 8
        for (int k = 0; k < 64; k++) {
            float a[4];
#pragma unroll
            for (int r = 0; r < 4; r++) a[r] = tmpS[(ty * 4 + r) * 130 + kc * 64 + k];
            float4 b = *reinterpret_cast<float4*>(&Bs2[k * 64 + tx * 4]);
#pragma unroll
            for (int r = 0; r < 4; r++) {
                acc2[r][0] += a[r] * b.x; acc2[r][1] += a[r] * b.y;
                acc2[r][2] += a[r] * b.z; acc2[r][3] += a[r] * b.w;
            }
        }
    }
    __syncthreads();

#pragma unroll
    for (int r = 0; r < 4; r++) {
        int row = nb + ty * 4 + r;
        float4 nx = make_float4(0.f, 0.f, 0.f, 0.f);
        if (row < NN) {
            float4 x0 = reinterpret_cast<float4*>(g_x)[row * 16 + tx];
            nx.x = x0.x + acc2[r][0] + fc2b[tx * 4 + 0];
            nx.y = x0.y + acc2[r][1] + fc2b[tx * 4 + 1];
            nx.z = x0.z + acc2[r][2] + fc2b[tx * 4 + 2];
            nx.w = x0.w + acc2[r][3] + fc2b[tx * 4 + 3];
            reinterpret_cast<float4*>(g_x)[row * 16 + tx] = nx;
        }
        As[(ty * 4 + r) * 68 + tx * 4 + 0] = nx.x;
        As[(ty * 4 + r) * 68 + tx * 4 + 1] = nx.y;
        As[(ty * 4 + r) * 68 + tx * 4 + 2] = nx.z;
        As[(ty * 4 + r) * 68 + tx * 4 + 3] = nx.w;
    }
    if (!do_pq) return;

    for (int cc = 0; cc < 4; cc++) {
        __syncthreads();
        const float* W = (cc < 2) ? pW1 : cW1;
        int koff = (cc & 1) ? 64 : 0;
        for (int t = tid; t < 4096; t += 256) {
            int k = t >> 6, c = t & 63;
            Bs2[k * 64 + c] = W[(koff + k) * 64 + c];
        }
        __syncthreads();
        float acc[4][4] = {};
#pragma unroll 8
        for (int k = 0; k < 64; k++) {
            float a[4];
#pragma unroll
            for (int r = 0; r < 4; r++) a[r] = As[(ty * 4 + r) * 68 + k];
            float4 b = *reinterpret_cast<float4*>(&Bs2[k * 64 + tx * 4]);
#pragma unroll
            for (int r = 0; r < 4; r++) {
                acc[r][0] += a[r] * b.x; acc[r][1] += a[r] * b.y;
                acc[r][2] += a[r] * b.z; acc[r][3] += a[r] * b.w;
            }
        }
#pragma unroll
        for (int r = 0; r < 4; r++) {
            int row = nb + ty * 4 + r;
            if (row < NN) {
                uint2 o;
                o.x = pack_h2(acc[r][0], acc[r][1]);
                o.y = pack_h2(acc[r][2], acc[r][3]);
                reinterpret_cast<uint2*>(g_PQ)[row * 64 + cc * 16 + tx] = o;
            }
        }
    }
}

// ---------------- out = x @ convW + convb ----------------
__global__ void k_out(const float* __restrict__ convW, const float* __restrict__ convb,
                      float* __restrict__ out) {
    __shared__ float As[64][68];
    __shared__ float Bs[64][64];
    int tid = threadIdx.x, tx = tid & 15, ty = tid >> 4;
    int nb = blockIdx.x * 64;

    for (int t = tid; t < 1024; t += 256) {
        int r = t >> 4, q = t & 15;
        float4 v = make_float4(0.f, 0.f, 0.f, 0.f);
        if (nb + r < NN) v = reinterpret_cast<const float4*>(g_x)[(nb + r) * 16 + q];
        As[r][q * 4 + 0] = v.x; As[r][q * 4 + 1] = v.y;
        As[r][q * 4 + 2] = v.z; As[r][q * 4 + 3] = v.w;
    }
    for (int cc = 0; cc < 2; cc++) {
        __syncthreads();
        for (int t = tid; t < 4096; t += 256) {
            int k = t >> 6, c = t & 63;
            Bs[k][c] = convW[k * 128 + cc * 64 + c];
        }
        __syncthreads();
        float acc[4][4] = {};
#pragma unroll 8
        for (int k = 0; k < 64; k++) {
            float a[4];
#pragma unroll
            for (int r = 0; r < 4; r++) a[r] = As[ty * 4 + r][k];
            float4 b = *reinterpret_cast<float4*>(&Bs[k][tx * 4]);
#pragma unroll
            for (int r = 0; r < 4; r++) {
                acc[r][0] += a[r] * b.x; acc[r][1] += a[r] * b.y;
                acc[r][2] += a[r] * b.z; acc[r][3] += a[r] * b.w;
            }
        }
#pragma unroll
        for (int r = 0; r < 4; r++) {
            int row = nb + ty * 4 + r;
            if (row < NN) {
                float4 o;
                o.x = acc[r][0] + convb[cc * 64 + tx * 4 + 0];
                o.y = acc[r][1] + convb[cc * 64 + tx * 4 + 1];
                o.z = acc[r][2] + convb[cc * 64 + tx * 4 + 2];
                o.w = acc[r][3] + convb[cc * 64 + tx * 4 + 3];
                reinterpret_cast<float4*>(out)[row * 32 + cc * 16 + tx] = o;
            }
        }
    }
}

// ---------------- host launcher ----------------
extern "C" void kernel_launch(void* const* d_in, const int* in_sizes, int n_in,
                              void* d_out, int out_size) {
    (void)in_sizes; (void)n_in; (void)out_size;
    const int*   nodes = (const int*)d_in[0];
    const int*   edges = (const int*)d_in[1];
    const int*   src   = edges;            // edges[0]
    const int*   dst   = edges + NE;       // edges[1]
    const float* emb   = (const float*)d_in[2];
    const float* pW1 = (const float*)d_in[3];
    const float* pg1 = (const float*)d_in[5],  *pbe1 = (const float*)d_in[6];
    const float* pW2 = (const float*)d_in[7];
    const float* pg2 = (const float*)d_in[9],  *pbe2 = (const float*)d_in[10];
    const float* cW1 = (const float*)d_in[11];
    const float* cg1 = (const float*)d_in[13], *cbe1 = (const float*)d_in[14];
    const float* cW2 = (const float*)d_in[15];
    const float* cg2 = (const float*)d_in[17], *cbe2 = (const float*)d_in[18];
    const float* fcW  = (const float*)d_in[19], *fcb  = (const float*)d_in[20];
    const float* fc2W = (const float*)d_in[21], *fc2b = (const float*)d_in[22];
    const float* convW = (const float*)d_in[23], *convb = (const float*)d_in[24];
    float* out = (float*)d_out;

    const int EDGE2_SMEM = 18432 + 16384 + 256 * 4 + 256 * 4 + 512 * 4;  // 38912
    const int NODE12_SMEM = (8448 + 4096) * 4;                           // 50176
    cudaFuncSetAttribute(k_edge2_dual, cudaFuncAttributeMaxDynamicSharedMemorySize, EDGE2_SMEM);
    cudaFuncSetAttribute(k_node12, cudaFuncAttributeMaxDynamicSharedMemorySize, NODE12_SMEM);

    k_zero<<<196, 256>>>();
    k_init<<<6258, 256>>>(nodes, emb, src, dst, pW2, cW2);
    {
        dim3 g(NBLK, 2);
        k_scanA<<<g, 1024>>>();
        k_scanB<<<1, 128>>>();
        k_scanC<<<g, 1024>>>();
    }
    k_fill<<<3125, 256>>>(src, dst);
    k_pq_dual<<<782, 256>>>(pW1, cW1);

    for (int it = 0; it < 2; it++) {
        k_stats1_dual<<<592, 512>>>();
        k_fin1<<<1, 128>>>(pg1, pbe1, cg1, cbe1);
        k_edge2_dual<<<6250, 256, EDGE2_SMEM>>>();
        k_fin2<<<1, 128>>>(pg2, pbe2, cg2, cbe2);
        {
            dim3 gg(6250, 2);
            k_gagg<<<gg, 256>>>();
        }
        k_node12<<<782, 256, NODE12_SMEM>>>(fcW, fcb, fc2W, fc2b, pW1, cW1, it == 0);
    }
    k_out<<<782, 256>>>(convW, convb, out);
}

// round 15
// speedup vs baseline: 1.0258x; 1.0040x over previous
#include <cuda_runtime.h>
#include <cuda_fp16.h>

#define NN 50000
#define NE 800000
#define EPS 1e-5f
#define NBLK 49   // ceil(NN/1024)

// ---------------- static scratch ----------------
__device__ __align__(16) float  g_x[NN * 64];       // node features
__device__ __align__(16) __half g_PQ[NN * 256];     // per-node [pP|pQ|cP|cQ] fp16
__device__ __align__(16) __half g_z2p[NE * 64];     // parent z2 (fp16), CSR(dst) order
__device__ __align__(16) __half g_z2c[NE * 64];     // child z2 (fp16), CSR(src) order
__device__ __align__(16) float  g_aggP[NN * 64];    // deg-normalized parent agg
__device__ __align__(16) float  g_aggC[NN * 64];
__device__ int   g_cntP[NN], g_cntC[NN];            // degree counts, then fill cursors
__device__ int   g_offP[NN + 1], g_offC[NN + 1];    // CSR offsets
__device__ __align__(8) int2 g_eP[NE];              // parent-dir (i=dst, j=src), sorted by i
__device__ __align__(8) int2 g_eC[NE];              // child-dir (i=src, j=dst), sorted by i
__device__ float g_dinvP[NN], g_dinvC[NN];
__device__ __align__(16) uint2 g_Bf[2048];          // pre-packed W2 MMA fragments (p|c)
__device__ int   g_bsum[2 * NBLK];                  // scan block sums
// [0:64]S1p [64:128]S1c [128:192]Q1p [192:256]Q1c
// [256:320]A1p [320:384]A1c [384:448]D1p [448:512]D1c
// [512:576]S2p [576:640]S2c [640:704]Q2p [704:768]Q2c
// [768:832]A2p [832:896]A2c [896:960]D2p [960:1024]D2c
__device__ __align__(16) float g_stats[1024];

__device__ __forceinline__ unsigned pack_h2(float a, float b) {
    __half2 h = __floats2half2_rn(a, b);
    return *reinterpret_cast<unsigned*>(&h);
}
__device__ __forceinline__ float2 upk(unsigned u) {
    return __half22float2(*reinterpret_cast<__half2*>(&u));
}

__device__ __forceinline__ void mma_f16(float* c, const unsigned* a, unsigned b0, unsigned b1) {
    asm volatile(
        "mma.sync.aligned.m16n8k16.row.col.f32.f16.f16.f32 "
        "{%0,%1,%2,%3}, {%4,%5,%6,%7}, {%8,%9}, {%0,%1,%2,%3};"
        : "+f"(c[0]), "+f"(c[1]), "+f"(c[2]), "+f"(c[3])
        : "r"(a[0]), "r"(a[1]), "r"(a[2]), "r"(a[3]), "r"(b0), "r"(b1));
}

// ---------------- zero counters + stats ----------------
__global__ void k_zero() {
    int t = blockIdx.x * blockDim.x + threadIdx.x;
    if (t < NN) { g_cntP[t] = 0; g_cntC[t] = 0; }
    if (t < 1024) g_stats[t] = 0.f;
}

// ---------------- fused setup: embed || degree || pack ----------------
__global__ void k_init(const int* __restrict__ nodes, const float* __restrict__ emb,
                       const int* __restrict__ src, const int* __restrict__ dst,
                       const float* __restrict__ pW2, const float* __restrict__ cW2) {
    int b = blockIdx.x;
    int tid = threadIdx.x;
    if (b < 3125) {
        int t = b * 256 + tid;
        int n = t >> 4, q = t & 15;
        reinterpret_cast<float4*>(g_x)[t] =
            reinterpret_cast<const float4*>(emb)[nodes[n] * 16 + q];
    } else if (b < 6250) {
        int e = (b - 3125) * 256 + tid;
        atomicAdd(&g_cntP[dst[e]], 1);
        atomicAdd(&g_cntC[src[e]], 1);
    } else {
        int t = (b - 6250) * 256 + tid;
        if (t < 2048) {
            int dir = t >> 10, u = t & 1023;
            int kk = u >> 8, nt = (u >> 5) & 7, ln = u & 31;
            int k0 = kk * 16 + (ln & 3) * 2;
            int n  = nt * 8 + (ln >> 2);
            const float* W = dir ? cW2 : pW2;
            uint2 v;
            v.x = pack_h2(W[k0 * 64 + n],       W[(k0 + 1) * 64 + n]);
            v.y = pack_h2(W[(k0 + 8) * 64 + n], W[(k0 + 9) * 64 + n]);
            g_Bf[t] = v;
        }
    }
}

// ---------------- parallel scan phase A: per-chunk block sums ----------------
__global__ void k_scanA() {
    __shared__ int ws[32];
    int half = blockIdx.y;
    int idx = blockIdx.x * 1024 + threadIdx.x;
    int lane = threadIdx.x & 31, w = threadIdx.x >> 5;
    const int* cnt = half ? g_cntC : g_cntP;
    int v = (idx < NN) ? cnt[idx] : 0;
#pragma unroll
    for (int o = 16; o > 0; o >>= 1) v += __shfl_down_sync(0xffffffff, v, o);
    if (lane == 0) ws[w] = v;
    __syncthreads();
    if (threadIdx.x < 32) {
        int s = ws[threadIdx.x];
#pragma unroll
        for (int o = 16; o > 0; o >>= 1) s += __shfl_down_sync(0xffffffff, s, o);
        if (threadIdx.x == 0) g_bsum[half * NBLK + blockIdx.x] = s;
    }
}

// ---------------- parallel scan phase B: 64-wide Hillis-Steele over block sums ----------------
__global__ void k_scanB() {
    __shared__ int sh[2][64];
    int t = threadIdx.x;           // 128 threads
    int half = t >> 6, i = t & 63;
    int v = (i < NBLK) ? g_bsum[half * NBLK + i] : 0;
    sh[half][i] = v;
    __syncthreads();
#pragma unroll
    for (int o = 1; o < 64; o <<= 1) {
        int add = (i >= o) ? sh[half][i - o] : 0;
        __syncthreads();
        sh[half][i] += add;
        __syncthreads();
    }
    if (i < NBLK) g_bsum[half * NBLK + i] = sh[half][i] - v;  // exclusive
    if (i == NBLK - 1) (half ? g_offC : g_offP)[NN] = sh[half][NBLK - 1];
}

// ---------------- parallel scan phase C: per-chunk scan + base; dinv; zero cursors ----------------
__global__ void k_scanC() {
    __shared__ int wsum[32];
    int half = blockIdx.y;
    int idx = blockIdx.x * 1024 + threadIdx.x;
    int lane = threadIdx.x & 31, w = threadIdx.x >> 5;
    int* cnt = half ? g_cntC : g_cntP;
    int* off = half ? g_offC : g_offP;
    float* dinv = half ? g_dinvC : g_dinvP;
    int v = (idx < NN) ? cnt[idx] : 0;
    int x = v;
#pragma unroll
    for (int o = 1; o < 32; o <<= 1) {
        int y = __shfl_up_sync(0xffffffff, x, o);
        if (lane >= o) x += y;
    }
    if (lane == 31) wsum[w] = x;
    __syncthreads();
    if (w == 0) {
        int s = wsum[lane];
#pragma unroll
        for (int o = 1; o < 32; o <<= 1) {
            int y = __shfl_up_sync(0xffffffff, s, o);
            if (lane >= o) s += y;
        }
        wsum[lane] = s;
    }
    __syncthreads();
    int incl = x + (w ? wsum[w - 1] : 0);
    int excl = incl - v + g_bsum[half * NBLK + blockIdx.x];
    if (idx < NN) {
        off[idx] = excl;
        dinv[idx] = v ? (1.f / v) : 0.f;
        cnt[idx] = 0;
    }
}

// fill direction-sorted edge lists (packed int2)
__global__ void k_fill(const int* __restrict__ src, const int* __restrict__ dst) {
    int e = blockIdx.x * blockDim.x + threadIdx.x;
    if (e < NE) {
        int s = src[e], d = dst[e];
        int p = atomicAdd(&g_cntP[d], 1);
        g_eP[g_offP[d] + p] = make_int2(d, s);
        int c = atomicAdd(&g_cntC[s], 1);
        g_eC[g_offC[s] + c] = make_int2(s, d);
    }
}

// ---------------- PQ = x @ [pW1t|pW1b|cW1t|cW1b]  (first iteration only) ----------------
__global__ void k_pq_dual(const float* __restrict__ pW1, const float* __restrict__ cW1) {
    __shared__ float As[64][68];
    __shared__ float Bs[64][64];
    int tid = threadIdx.x;
    int tx = tid & 15, ty = tid >> 4;
    int nb = blockIdx.x * 64;

    for (int t = tid; t < 1024; t += 256) {
        int r = t >> 4, q = t & 15;
        float4 v = make_float4(0.f, 0.f, 0.f, 0.f);
        if (nb + r < NN) v = reinterpret_cast<const float4*>(g_x)[(nb + r) * 16 + q];
        As[r][q * 4 + 0] = v.x; As[r][q * 4 + 1] = v.y;
        As[r][q * 4 + 2] = v.z; As[r][q * 4 + 3] = v.w;
    }
    for (int cc = 0; cc < 4; cc++) {
        __syncthreads();
        const float* W = (cc < 2) ? pW1 : cW1;
        int koff = (cc & 1) ? 64 : 0;
        for (int t = tid; t < 4096; t += 256) {
            int k = t >> 6, c = t & 63;
            Bs[k][c] = W[(koff + k) * 64 + c];
        }
        __syncthreads();
        float acc[4][4] = {};
#pragma unroll 8
        for (int k = 0; k < 64; k++) {
            float a[4];
#pragma unroll
            for (int r = 0; r < 4; r++) a[r] = As[ty * 4 + r][k];
            float4 b = *reinterpret_cast<float4*>(&Bs[k][tx * 4]);
#pragma unroll
            for (int r = 0; r < 4; r++) {
                acc[r][0] += a[r] * b.x; acc[r][1] += a[r] * b.y;
                acc[r][2] += a[r] * b.z; acc[r][3] += a[r] * b.w;
            }
        }
#pragma unroll
        for (int r = 0; r < 4; r++) {
            int row = nb + ty * 4 + r;
            if (row < NN) {
                uint2 o;
                o.x = pack_h2(acc[r][0], acc[r][1]);
                o.y = pack_h2(acc[r][2], acc[r][3]);
                reinterpret_cast<uint2*>(g_PQ)[row * 64 + cc * 16 + tx] = o;
            }
        }
    }
}

// ---------------- z1 stats, both directions, contiguous chunks, 4-edge unroll ----------------
__global__ void k_stats1_dual() {
    __shared__ float red[256];
    int tid = threadIdx.x;
    if (tid < 256) red[tid] = 0.f;
    __syncthreads();
    int lane = tid & 31;
    int gw = (blockIdx.x * blockDim.x + tid) >> 5;
    int nw = (gridDim.x * blockDim.x) >> 5;
    int chunk = (NE + nw - 1) / nw;
    int e0 = gw * chunk, e1 = min(NE, e0 + chunk);
    const unsigned* PQw = reinterpret_cast<const unsigned*>(g_PQ);  // 128 uints/row
    float2 sp = {0.f, 0.f}, qp = {0.f, 0.f}, sc = {0.f, 0.f}, qc = {0.f, 0.f};

    int e = e0;
    for (; e + 4 <= e1; e += 4) {
        int2 ep[4], ec[4];
#pragma unroll
        for (int u = 0; u < 4; u++) { ep[u] = g_eP[e + u]; ec[u] = g_eC[e + u]; }
        float2 pP[4], pQ[4], cP[4], cQ[4];
#pragma unroll
        for (int u = 0; u < 4; u++) {
            pP[u] = upk(PQw[ep[u].x * 128 + lane]);
            pQ[u] = upk(PQw[ep[u].y * 128 + 32 + lane]);
            cP[u] = upk(PQw[ec[u].x * 128 + 64 + lane]);
            cQ[u] = upk(PQw[ec[u].y * 128 + 96 + lane]);
        }
#pragma unroll
        for (int u = 0; u < 4; u++) {
            float2 v;
            v.x = pP[u].x + pQ[u].x; v.y = pP[u].y + pQ[u].y;
            sp.x += v.x; sp.y += v.y; qp.x += v.x * v.x; qp.y += v.y * v.y;
            v.x = cP[u].x + cQ[u].x; v.y = cP[u].y + cQ[u].y;
            sc.x += v.x; sc.y += v.y; qc.x += v.x * v.x; qc.y += v.y * v.y;
        }
    }
    for (; e < e1; e++) {
        int2 ep = g_eP[e], ec = g_eC[e];
        float2 pP = upk(PQw[ep.x * 128 + lane]);
        float2 pQ = upk(PQw[ep.y * 128 + 32 + lane]);
        float2 cP = upk(PQw[ec.x * 128 + 64 + lane]);
        float2 cQ = upk(PQw[ec.y * 128 + 96 + lane]);
        float2 v;
        v.x = pP.x + pQ.x; v.y = pP.y + pQ.y;
        sp.x += v.x; sp.y += v.y; qp.x += v.x * v.x; qp.y += v.y * v.y;
        v.x = cP.x + cQ.x; v.y = cP.y + cQ.y;
        sc.x += v.x; sc.y += v.y; qc.x += v.x * v.x; qc.y += v.y * v.y;
    }
    atomicAdd(&red[2 * lane],           sp.x); atomicAdd(&red[2 * lane + 1],       sp.y);
    atomicAdd(&red[64 + 2 * lane],      sc.x); atomicAdd(&red[64 + 2 * lane + 1],  sc.y);
    atomicAdd(&red[128 + 2 * lane],     qp.x); atomicAdd(&red[128 + 2 * lane + 1], qp.y);
    atomicAdd(&red[192 + 2 * lane],     qc.x); atomicAdd(&red[192 + 2 * lane + 1], qc.y);
    __syncthreads();
    if (tid < 256) atomicAdd(&g_stats[tid], red[tid]);
}

// ---------------- finalize BN1 ----------------
__global__ void k_fin1(const float* __restrict__ pg1, const float* __restrict__ pbe1,
                       const float* __restrict__ cg1, const float* __restrict__ cbe1) {
    int t = threadIdx.x;  // 128
    const float invE = 1.f / NE;
    if (t < 64) {
        float s = g_stats[t], q = g_stats[128 + t];
        float mu = s * invE;
        float rs = rsqrtf(q * invE - mu * mu + EPS);
        float A = pg1[t] * rs;
        g_stats[256 + t] = A;
        g_stats[384 + t] = pbe1[t] - A * mu;
        g_stats[t] = 0.f; g_stats[128 + t] = 0.f;
    } else {
        int c = t - 64;
        float s = g_stats[64 + c], q = g_stats[192 + c];
        float mu = s * invE;
        float rs = rsqrtf(q * invE - mu * mu + EPS);
        float A = cg1[c] * rs;
        g_stats[320 + c] = A;
        g_stats[448 + c] = cbe1[c] - A * mu;
        g_stats[64 + c] = 0.f; g_stats[192 + c] = 0.f;
    }
}

// ---------------- edge MLP, one direction per block (grid.y): BN1+ReLU -> fp16 MMA -> z2 + stats
// SMEM: h1h (18432B) | Bf uint2[1024] (8192B) | prm[128] | sSt[128] | sIdx[256]  = 28672B
__global__ void k_edge2_dual() {
    extern __shared__ char smraw[];
    __half* h1h = reinterpret_cast<__half*>(smraw);                  // 128*72 halfs
    uint2*  Bf  = reinterpret_cast<uint2*>(smraw + 18432);           // 1024
    float*  prm = reinterpret_cast<float*>(smraw + 18432 + 8192);    // 128
    float*  sSt = prm + 128;                                         // 128
    int*    sIdx = reinterpret_cast<int*>(sSt + 128);                // 256

    int tid = threadIdx.x;
    int lane = tid & 31;
    int wid = tid >> 5;
    int dir = blockIdx.y;
    int e0 = blockIdx.x * 128;

    if (tid < 64) {
        prm[tid]      = g_stats[256 + dir * 64 + tid];  // A1 (p or c)
        prm[64 + tid] = g_stats[384 + dir * 64 + tid];  // D1
    }
    if (tid < 128) {
        sSt[tid] = 0.f;
        int2 ep = dir ? g_eC[e0 + tid] : g_eP[e0 + tid];
        sIdx[tid]       = ep.x;
        sIdx[128 + tid] = ep.y;
    }
    // copy this direction's pre-packed fragments (8 KB) via uint4
    {
        const uint4* Bg = reinterpret_cast<const uint4*>(g_Bf) + dir * 512;
        uint4* Bs4 = reinterpret_cast<uint4*>(Bf);
#pragma unroll
        for (int t = tid; t < 512; t += 256) Bs4[t] = Bg[t];
    }
    __syncthreads();

    const uint4* PQ4 = reinterpret_cast<const uint4*>(g_PQ);  // 32 uint4/row
    int m0 = wid * 16;
    int lr = (lane & 7) + ((lane >> 3) & 1) * 8;
    int lc = (lane >> 4) * 8;
    int row0 = e0 + m0 + (lane >> 2);
    int pbase = dir * 16;

    // phase 1: h1 = relu(A*(P[i]+Q[j]) + D) stored fp16; uint4 gathers
    for (int t = tid; t < 1024; t += 256) {
        int er = t >> 3, q = t & 7;
        int i = sIdx[er], j = sIdx[128 + er];
        uint4 pu = PQ4[i * 32 + pbase + q];
        uint4 qu = PQ4[j * 32 + pbase + 8 + q];
        float2 p0 = upk(pu.x), p1 = upk(pu.y), p2 = upk(pu.z), p3 = upk(pu.w);
        float2 r0 = upk(qu.x), r1 = upk(qu.y), r2 = upk(qu.z), r3 = upk(qu.w);
        int c = q * 8;
        float h0 = fmaxf(fmaf(prm[c + 0], p0.x + r0.x, prm[64 + c + 0]), 0.f);
        float h1 = fmaxf(fmaf(prm[c + 1], p0.y + r0.y, prm[64 + c + 1]), 0.f);
        float h2 = fmaxf(fmaf(prm[c + 2], p1.x + r1.x, prm[64 + c + 2]), 0.f);
        float h3 = fmaxf(fmaf(prm[c + 3], p1.y + r1.y, prm[64 + c + 3]), 0.f);
        float h4 = fmaxf(fmaf(prm[c + 4], p2.x + r2.x, prm[64 + c + 4]), 0.f);
        float h5 = fmaxf(fmaf(prm[c + 5], p2.y + r2.y, prm[64 + c + 5]), 0.f);
        float h6 = fmaxf(fmaf(prm[c + 6], p3.x + r3.x, prm[64 + c + 6]), 0.f);
        float h7 = fmaxf(fmaf(prm[c + 7], p3.y + r3.y, prm[64 + c + 7]), 0.f);
        uint4 o;
        o.x = pack_h2(h0, h1); o.y = pack_h2(h2, h3);
        o.z = pack_h2(h4, h5); o.w = pack_h2(h6, h7);
        *reinterpret_cast<uint4*>(&h1h[er * 72 + c]) = o;
    }
    __syncthreads();

    unsigned a[4][4];
#pragma unroll
    for (int kk = 0; kk < 4; kk++) {
        unsigned addr = (unsigned)__cvta_generic_to_shared(
            &h1h[(m0 + lr) * 72 + kk * 16 + lc]);
        asm volatile("ldmatrix.sync.aligned.m8n8.x4.shared.b16 {%0,%1,%2,%3}, [%4];"
                     : "=r"(a[kk][0]), "=r"(a[kk][1]), "=r"(a[kk][2]), "=r"(a[kk][3])
                     : "r"(addr));
    }
    float acc[8][4];
#pragma unroll
    for (int nt = 0; nt < 8; nt++)
#pragma unroll
        for (int u = 0; u < 4; u++) acc[nt][u] = 0.f;

#pragma unroll
    for (int kk = 0; kk < 4; kk++) {
#pragma unroll
        for (int nt = 0; nt < 8; nt++) {
            uint2 b = Bf[(kk * 8 + nt) * 32 + lane];
            mma_f16(acc[nt], a[kk], b.x, b.y);
        }
    }

    __half* z2 = dir ? g_z2c : g_z2p;
#pragma unroll
    for (int nt = 0; nt < 8; nt++) {
        int col = nt * 8 + (lane & 3) * 2;
        __half2 hv0 = __floats2half2_rn(acc[nt][0], acc[nt][1]);
        __half2 hv1 = __floats2half2_rn(acc[nt][2], acc[nt][3]);
        *reinterpret_cast<__half2*>(&z2[row0 * 64 + col])       = hv0;
        *reinterpret_cast<__half2*>(&z2[(row0 + 8) * 64 + col]) = hv1;
        float2 r0 = __half22float2(hv0), r1 = __half22float2(hv1);
        float se = r0.x + r1.x, qe = r0.x * r0.x + r1.x * r1.x;
        float so = r0.y + r1.y, qo = r0.y * r0.y + r1.y * r1.y;
#pragma unroll
        for (int off = 4; off < 32; off <<= 1) {
            se += __shfl_xor_sync(0xffffffff, se, off);
            qe += __shfl_xor_sync(0xffffffff, qe, off);
            so += __shfl_xor_sync(0xffffffff, so, off);
            qo += __shfl_xor_sync(0xffffffff, qo, off);
        }
        if (lane < 4) {
            atomicAdd(&sSt[col], se);
            atomicAdd(&sSt[64 + col], qe);
            atomicAdd(&sSt[col + 1], so);
            atomicAdd(&sSt[64 + col + 1], qo);
        }
    }
    __syncthreads();

    // flush: sSt[0:64]=S2, sSt[64:128]=Q2 for this dir
    if (tid < 64)        atomicAdd(&g_stats[512 + dir * 64 + tid], sSt[tid]);
    else if (tid < 128)  atomicAdd(&g_stats[640 + dir * 64 + (tid - 64)], sSt[tid]);
}

// ---------------- finalize BN2 ----------------
__global__ void k_fin2(const float* __restrict__ pg2, const float* __restrict__ pbe2,
                       const float* __restrict__ cg2, const float* __restrict__ cbe2) {
    int t = threadIdx.x;  // 128
    const float invE = 1.f / NE;
    if (t < 64) {
        float s = g_stats[512 + t], q = g_stats[640 + t];
        float mu = s * invE;
        float rs = rsqrtf(q * invE - mu * mu + EPS);
        float A = pg2[t] * rs;
        g_stats[768 + t] = A;
        g_stats[896 + t] = pbe2[t] - A * mu;
        g_stats[512 + t] = 0.f; g_stats[640 + t] = 0.f;
    } else {
        int c = t - 64;
        float s = g_stats[576 + c], q = g_stats[704 + c];
        float mu = s * invE;
        float rs = rsqrtf(q * invE - mu * mu + EPS);
        float A = cg2[c] * rs;
        g_stats[832 + c] = A;
        g_stats[960 + c] = cbe2[c] - A * mu;
        g_stats[576 + c] = 0.f; g_stats[704 + c] = 0.f;
    }
}

// ---------------- streaming aggregation: one warp per node, 8-row unroll, split by dir -----
__global__ void __launch_bounds__(256) k_gagg() {
    int lane = threadIdx.x & 31;
    int n = blockIdx.x * 8 + (threadIdx.x >> 5);
    if (blockIdx.y == 0) {
        float2 A = *reinterpret_cast<const float2*>(&g_stats[768 + 2 * lane]);
        float2 D = *reinterpret_cast<const float2*>(&g_stats[896 + 2 * lane]);
        int s = g_offP[n], t = g_offP[n + 1];
        float ax = 0.f, ay = 0.f;
        int k = s;
        for (; k + 8 <= t; k += 8) {
            float2 f[8];
#pragma unroll
            for (int u = 0; u < 8; u++)
                f[u] = upk(*reinterpret_cast<const unsigned*>(&g_z2p[(k + u) * 64 + lane * 2]));
#pragma unroll
            for (int u = 0; u < 8; u++) {
                ax += fmaxf(fmaf(A.x, f[u].x, D.x), 0.f);
                ay += fmaxf(fmaf(A.y, f[u].y, D.y), 0.f);
            }
        }
        for (; k < t; k++) {
            float2 f0 = upk(*reinterpret_cast<const unsigned*>(&g_z2p[k * 64 + lane * 2]));
            ax += fmaxf(fmaf(A.x, f0.x, D.x), 0.f);
            ay += fmaxf(fmaf(A.y, f0.y, D.y), 0.f);
        }
        float di = g_dinvP[n];
        *reinterpret_cast<float2*>(&g_aggP[n * 64 + lane * 2]) = make_float2(ax * di, ay * di);
    } else {
        float2 A = *reinterpret_cast<const float2*>(&g_stats[832 + 2 * lane]);
        float2 D = *reinterpret_cast<const float2*>(&g_stats[960 + 2 * lane]);
        int s = g_offC[n], t = g_offC[n + 1];
        float ax = 0.f, ay = 0.f;
        int k = s;
        for (; k + 8 <= t; k += 8) {
            float2 f[8];
#pragma unroll
            for (int u = 0; u < 8; u++)
                f[u] = upk(*reinterpret_cast<const unsigned*>(&g_z2c[(k + u) * 64 + lane * 2]));
#pragma unroll
            for (int u = 0; u < 8; u++) {
                ax += fmaxf(fmaf(A.x, f[u].x, D.x), 0.f);
                ay += fmaxf(fmaf(A.y, f[u].y, D.y), 0.f);
            }
        }
        for (; k < t; k++) {
            float2 f0 = upk(*reinterpret_cast<const unsigned*>(&g_z2c[k * 64 + lane * 2]));
            ax += fmaxf(fmaf(A.x, f0.x, D.x), 0.f);
            ay += fmaxf(fmaf(A.y, f0.y, D.y), 0.f);
        }
        float di = g_dinvC[n];
        *reinterpret_cast<float2*>(&g_aggC[n * 64 + lane * 2]) = make_float2(ax * di, ay * di);
    }
}

// ---------------- fused node update + next-iter PQ ----------------
__global__ void k_node12(const float* __restrict__ fcW, const float* __restrict__ fcb,
                         const float* __restrict__ fc2W, const float* __restrict__ fc2b,
                         const float* __restrict__ pW1, const float* __restrict__ cW1,
                         int do_pq) {
    extern __shared__ float sm[];
    float* As   = sm;            // [64][68]
    float* Bs   = sm + 4352;     // [64][64]
    float* tmpS = sm;            // aliases As+Bs, [64][130]
    float* Bs2  = sm + 8448;     // [64][64]

    int tid = threadIdx.x, tx = tid & 15, ty = tid >> 4;
    int nb = blockIdx.x * 64;

    float acc8[4][8] = {};
    for (int kc = 0; kc < 3; kc++) {
        __syncthreads();
        for (int t = tid; t < 1024; t += 256) {
            int r = t >> 4, q = t & 15;
            int row = nb + r;
            float4 v = make_float4(0.f, 0.f, 0.f, 0.f);
            if (row < NN) {
                if (kc == 0)      v = reinterpret_cast<const float4*>(g_x)[row * 16 + q];
                else if (kc == 1) v = reinterpret_cast<const float4*>(g_aggP)[row * 16 + q];
                else              v = reinterpret_cast<const float4*>(g_aggC)[row * 16 + q];
            }
            As[r * 68 + q * 4 + 0] = v.x; As[r * 68 + q * 4 + 1] = v.y;
            As[r * 68 + q * 4 + 2] = v.z; As[r * 68 + q * 4 + 3] = v.w;
        }
        for (int cc = 0; cc < 2; cc++) {
            __syncthreads();
            for (int t = tid; t < 4096; t += 256) {
                int k = t >> 6, c = t & 63;
                Bs[k * 64 + c] = fcW[(kc * 64 + k) * 128 + cc * 64 + c];
            }
            __syncthreads();
#pragma unroll 8
            for (int k = 0; k < 64; k++) {
                float a[4];
#pragma unroll
                for (int r = 0; r < 4; r++) a[r] = As[(ty * 4 + r) * 68 + k];
                float4 b = *reinterpret_cast<float4*>(&Bs[k * 64 + tx * 4]);
#pragma unroll
                for (int r = 0; r < 4; r++) {
                    acc8[r][cc * 4 + 0] += a[r] * b.x; acc8[r][cc * 4 + 1] += a[r] * b.y;
                    acc8[r][cc * 4 + 2] += a[r] * b.z; acc8[r][cc * 4 + 3] += a[r] * b.w;
                }
            }
        }
    }
    __syncthreads();
#pragma unroll
    for (int r = 0; r < 4; r++) {
#pragma unroll
        for (int cc = 0; cc < 2; cc++) {
            int c0 = cc * 64 + tx * 4;
#pragma unroll
            for (int u = 0; u < 4; u++)
                tmpS[(ty * 4 + r) * 130 + c0 + u] =
                    fmaxf(acc8[r][cc * 4 + u] + fcb[c0 + u], 0.f);
        }
    }

    float acc2[4][4] = {};
    for (int kc = 0; kc < 2; kc++) {
        __syncthreads();
        for (int t = tid; t < 4096; t += 256) {
            int k = t >> 6, c = t & 63;
            Bs2[k * 64 + c] = fc2W[(kc * 64 + k) * 64 + c];
        }
        __syncthreads();
#pragma unroll 8
        for (int k = 0; k < 64; k++) {
            float a[4];
#pragma unroll
            for (int r = 0; r < 4; r++) a[r] = tmpS[(ty * 4 + r) * 130 + kc * 64 + k];
            float4 b = *reinterpret_cast<float4*>(&Bs2[k * 64 + tx * 4]);
#pragma unroll
            for (int r = 0; r < 4; r++) {
                acc2[r][0] += a[r] * b.x; acc2[r][1] += a[r] * b.y;
                acc2[r][2] += a[r] * b.z; acc2[r][3] += a[r] * b.w;
            }
        }
    }
    __syncthreads();

#pragma unroll
    for (int r = 0; r < 4; r++) {
        int row = nb + ty * 4 + r;
        float4 nx = make_float4(0.f, 0.f, 0.f, 0.f);
        if (row < NN) {
            float4 x0 = reinterpret_cast<float4*>(g_x)[row * 16 + tx];
            nx.x = x0.x + acc2[r][0] + fc2b[tx * 4 + 0];
            nx.y = x0.y + acc2[r][1] + fc2b[tx * 4 + 1];
            nx.z = x0.z + acc2[r][2] + fc2b[tx * 4 + 2];
            nx.w = x0.w + acc2[r][3] + fc2b[tx * 4 + 3];
            reinterpret_cast<float4*>(g_x)[row * 16 + tx] = nx;
        }
        As[(ty * 4 + r) * 68 + tx * 4 + 0] = nx.x;
        As[(ty * 4 + r) * 68 + tx * 4 + 1] = nx.y;
        As[(ty * 4 + r) * 68 + tx * 4 + 2] = nx.z;
        As[(ty * 4 + r) * 68 + tx * 4 + 3] = nx.w;
    }
    if (!do_pq) return;

    for (int cc = 0; cc < 4; cc++) {
        __syncthreads();
        const float* W = (cc < 2) ? pW1 : cW1;
        int koff = (cc & 1) ? 64 : 0;
        for (int t = tid; t < 4096; t += 256) {
            int k = t >> 6, c = t & 63;
            Bs2[k * 64 + c] = W[(koff + k) * 64 + c];
        }
        __syncthreads();
        float acc[4][4] = {};
#pragma unroll 8
        for (int k = 0; k < 64; k++) {
            float a[4];
#pragma unroll
            for (int r = 0; r < 4; r++) a[r] = As[(ty * 4 + r) * 68 + k];
            float4 b = *reinterpret_cast<float4*>(&Bs2[k * 64 + tx * 4]);
#pragma unroll
            for (int r = 0; r < 4; r++) {
                acc[r][0] += a[r] * b.x; acc[r][1] += a[r] * b.y;
                acc[r][2] += a[r] * b.z; acc[r][3] += a[r] * b.w;
            }
        }
#pragma unroll
        for (int r = 0; r < 4; r++) {
            int row = nb + ty * 4 + r;
            if (row < NN) {
                uint2 o;
                o.x = pack_h2(acc[r][0], acc[r][1]);
                o.y = pack_h2(acc[r][2], acc[r][3]);
                reinterpret_cast<uint2*>(g_PQ)[row * 64 + cc * 16 + tx] = o;
            }
        }
    }
}

// ---------------- out = x @ convW + convb ----------------
__global__ void k_out(const float* __restrict__ convW, const float* __restrict__ convb,
                      float* __restrict__ out) {
    __shared__ float As[64][68];
    __shared__ float Bs[64][64];
    int tid = threadIdx.x, tx = tid & 15, ty = tid >> 4;
    int nb = blockIdx.x * 64;

    for (int t = tid; t < 1024; t += 256) {
        int r = t >> 4, q = t & 15;
        float4 v = make_float4(0.f, 0.f, 0.f, 0.f);
        if (nb + r < NN) v = reinterpret_cast<const float4*>(g_x)[(nb + r) * 16 + q];
        As[r][q * 4 + 0] = v.x; As[r][q * 4 + 1] = v.y;
        As[r][q * 4 + 2] = v.z; As[r][q * 4 + 3] = v.w;
    }
    for (int cc = 0; cc < 2; cc++) {
        __syncthreads();
        for (int t = tid; t < 4096; t += 256) {
            int k = t >> 6, c = t & 63;
            Bs[k][c] = convW[k * 128 + cc * 64 + c];
        }
        __syncthreads();
        float acc[4][4] = {};
#pragma unroll 8
        for (int k = 0; k < 64; k++) {
            float a[4];
#pragma unroll
            for (int r = 0; r < 4; r++) a[r] = As[ty * 4 + r][k];
            float4 b = *reinterpret_cast<float4*>(&Bs[k][tx * 4]);
#pragma unroll
            for (int r = 0; r < 4; r++) {
                acc[r][0] += a[r] * b.x; acc[r][1] += a[r] * b.y;
                acc[r][2] += a[r] * b.z; acc[r][3] += a[r] * b.w;
            }
        }
#pragma unroll
        for (int r = 0; r < 4; r++) {
            int row = nb + ty * 4 + r;
            if (row < NN) {
                float4 o;
                o.x = acc[r][0] + convb[cc * 64 + tx * 4 + 0];
                o.y = acc[r][1] + convb[cc * 64 + tx * 4 + 1];
                o.z = acc[r][2] + convb[cc * 64 + tx * 4 + 2];
                o.w = acc[r][3] + convb[cc * 64 + tx * 4 + 3];
                reinterpret_cast<float4*>(out)[row * 32 + cc * 16 + tx] = o;
            }
        }
    }
}

// ---------------- host launcher ----------------
extern "C" void kernel_launch(void* const* d_in, const int* in_sizes, int n_in,
                              void* d_out, int out_size) {
    (void)in_sizes; (void)n_in; (void)out_size;
    const int*   nodes = (const int*)d_in[0];
    const int*   edges = (const int*)d_in[1];
    const int*   src   = edges;            // edges[0]
    const int*   dst   = edges + NE;       // edges[1]
    const float* emb   = (const float*)d_in[2];
    const float* pW1 = (const float*)d_in[3];
    const float* pg1 = (const float*)d_in[5],  *pbe1 = (const float*)d_in[6];
    const float* pW2 = (const float*)d_in[7];
    const float* pg2 = (const float*)d_in[9],  *pbe2 = (const float*)d_in[10];
    const float* cW1 = (const float*)d_in[11];
    const float* cg1 = (const float*)d_in[13], *cbe1 = (const float*)d_in[14];
    const float* cW2 = (const float*)d_in[15];
    const float* cg2 = (const float*)d_in[17], *cbe2 = (const float*)d_in[18];
    const float* fcW  = (const float*)d_in[19], *fcb  = (const float*)d_in[20];
    const float* fc2W = (const float*)d_in[21], *fc2b = (const float*)d_in[22];
    const float* convW = (const float*)d_in[23], *convb = (const float*)d_in[24];
    float* out = (float*)d_out;

    const int EDGE2_SMEM = 18432 + 8192 + 128 * 4 + 128 * 4 + 256 * 4;  // 28672
    const int NODE12_SMEM = (8448 + 4096) * 4;                          // 50176
    cudaFuncSetAttribute(k_edge2_dual, cudaFuncAttributeMaxDynamicSharedMemorySize, EDGE2_SMEM);
    cudaFuncSetAttribute(k_node12, cudaFuncAttributeMaxDynamicSharedMemorySize, NODE12_SMEM);

    k_zero<<<196, 256>>>();
    k_init<<<6258, 256>>>(nodes, emb, src, dst, pW2, cW2);
    {
        dim3 g(NBLK, 2);
        k_scanA<<<g, 1024>>>();
        k_scanB<<<1, 128>>>();
        k_scanC<<<g, 1024>>>();
    }
    k_fill<<<3125, 256>>>(src, dst);
    k_pq_dual<<<782, 256>>>(pW1, cW1);

    for (int it = 0; it < 2; it++) {
        k_stats1_dual<<<592, 512>>>();
        k_fin1<<<1, 128>>>(pg1, pbe1, cg1, cbe1);
        {
            dim3 ge(6250, 2);
            k_edge2_dual<<<ge, 256, EDGE2_SMEM>>>();
        }
        k_fin2<<<1, 128>>>(pg2, pbe2, cg2, cbe2);
        {
            dim3 gg(6250, 2);
            k_gagg<<<gg, 256>>>();
        }
        k_node12<<<782, 256, NODE12_SMEM>>>(fcW, fcb, fc2W, fc2b, pW1, cW1, it == 0);
    }
    k_out<<<782, 256>>>(convW, convb, out);
}

// round 16
// speedup vs baseline: 1.0292x; 1.0033x over previous
#include <cuda_runtime.h>
#include <cuda_fp16.h>

#define NN 50000
#define NE 800000
#define EPS 1e-5f
#define NBLK 49   // ceil(NN/1024)

// ---------------- static scratch ----------------
__device__ __align__(16) float  g_x[NN * 64];       // node features
__device__ __align__(16) __half g_PQ[NN * 256];     // per-node [pP|pQ|cP|cQ] fp16
__device__ __align__(16) __half g_z2p[NE * 64];     // parent z2 (fp16), CSR(dst) order
__device__ __align__(16) __half g_z2c[NE * 64];     // child z2 (fp16), CSR(src) order
__device__ __align__(16) float  g_aggP[NN * 64];    // deg-normalized parent agg
__device__ __align__(16) float  g_aggC[NN * 64];
__device__ int   g_cntP[NN], g_cntC[NN];            // degree counts, then fill cursors
__device__ int   g_offP[NN + 1], g_offC[NN + 1];    // CSR offsets
__device__ __align__(8) int2 g_eP[NE];              // parent-dir (i=dst, j=src), sorted by i
__device__ __align__(8) int2 g_eC[NE];              // child-dir (i=src, j=dst), sorted by i
__device__ float g_dinvP[NN], g_dinvC[NN];
__device__ __align__(16) uint2 g_Bf[2048];          // pre-packed W2 MMA fragments (p|c)
__device__ int   g_bsum[2 * NBLK];                  // scan block sums
// [0:64]S1p [64:128]S1c [128:192]Q1p [192:256]Q1c
// [256:320]A1p [320:384]A1c [384:448]D1p [448:512]D1c
// [512:576]S2p [576:640]S2c [640:704]Q2p [704:768]Q2c
// [768:832]A2p [832:896]A2c [896:960]D2p [960:1024]D2c
__device__ __align__(16) float g_stats[1024];

__device__ __forceinline__ unsigned pack_h2(float a, float b) {
    __half2 h = __floats2half2_rn(a, b);
    return *reinterpret_cast<unsigned*>(&h);
}
__device__ __forceinline__ float2 upk(unsigned u) {
    return __half22float2(*reinterpret_cast<__half2*>(&u));
}

__device__ __forceinline__ void mma_f16(float* c, const unsigned* a, unsigned b0, unsigned b1) {
    asm volatile(
        "mma.sync.aligned.m16n8k16.row.col.f32.f16.f16.f32 "
        "{%0,%1,%2,%3}, {%4,%5,%6,%7}, {%8,%9}, {%0,%1,%2,%3};"
        : "+f"(c[0]), "+f"(c[1]), "+f"(c[2]), "+f"(c[3])
        : "r"(a[0]), "r"(a[1]), "r"(a[2]), "r"(a[3]), "r"(b0), "r"(b1));
}

// ---------------- zero counters + stats ----------------
__global__ void k_zero() {
    int t = blockIdx.x * blockDim.x + threadIdx.x;
    if (t < NN) { g_cntP[t] = 0; g_cntC[t] = 0; }
    if (t < 1024) g_stats[t] = 0.f;
}

// ---------------- fused setup: embed || degree || pack ----------------
__global__ void k_init(const int* __restrict__ nodes, const float* __restrict__ emb,
                       const int* __restrict__ src, const int* __restrict__ dst,
                       const float* __restrict__ pW2, const float* __restrict__ cW2) {
    int b = blockIdx.x;
    int tid = threadIdx.x;
    if (b < 3125) {
        int t = b * 256 + tid;
        int n = t >> 4, q = t & 15;
        reinterpret_cast<float4*>(g_x)[t] =
            reinterpret_cast<const float4*>(emb)[nodes[n] * 16 + q];
    } else if (b < 6250) {
        int e = (b - 3125) * 256 + tid;
        atomicAdd(&g_cntP[dst[e]], 1);
        atomicAdd(&g_cntC[src[e]], 1);
    } else {
        int t = (b - 6250) * 256 + tid;
        if (t < 2048) {
            int dir = t >> 10, u = t & 1023;
            int kk = u >> 8, nt = (u >> 5) & 7, ln = u & 31;
            int k0 = kk * 16 + (ln & 3) * 2;
            int n  = nt * 8 + (ln >> 2);
            const float* W = dir ? cW2 : pW2;
            uint2 v;
            v.x = pack_h2(W[k0 * 64 + n],       W[(k0 + 1) * 64 + n]);
            v.y = pack_h2(W[(k0 + 8) * 64 + n], W[(k0 + 9) * 64 + n]);
            g_Bf[t] = v;
        }
    }
}

// ---------------- parallel scan phase A: per-chunk block sums ----------------
__global__ void k_scanA() {
    __shared__ int ws[32];
    int half = blockIdx.y;
    int idx = blockIdx.x * 1024 + threadIdx.x;
    int lane = threadIdx.x & 31, w = threadIdx.x >> 5;
    const int* cnt = half ? g_cntC : g_cntP;
    int v = (idx < NN) ? cnt[idx] : 0;
#pragma unroll
    for (int o = 16; o > 0; o >>= 1) v += __shfl_down_sync(0xffffffff, v, o);
    if (lane == 0) ws[w] = v;
    __syncthreads();
    if (threadIdx.x < 32) {
        int s = ws[threadIdx.x];
#pragma unroll
        for (int o = 16; o > 0; o >>= 1) s += __shfl_down_sync(0xffffffff, s, o);
        if (threadIdx.x == 0) g_bsum[half * NBLK + blockIdx.x] = s;
    }
}

// ---------------- parallel scan phase B: 64-wide Hillis-Steele over block sums ----------------
__global__ void k_scanB() {
    __shared__ int sh[2][64];
    int t = threadIdx.x;           // 128 threads
    int half = t >> 6, i = t & 63;
    int v = (i < NBLK) ? g_bsum[half * NBLK + i] : 0;
    sh[half][i] = v;
    __syncthreads();
#pragma unroll
    for (int o = 1; o < 64; o <<= 1) {
        int add = (i >= o) ? sh[half][i - o] : 0;
        __syncthreads();
        sh[half][i] += add;
        __syncthreads();
    }
    if (i < NBLK) g_bsum[half * NBLK + i] = sh[half][i] - v;  // exclusive
    if (i == NBLK - 1) (half ? g_offC : g_offP)[NN] = sh[half][NBLK - 1];
}

// ---------------- parallel scan phase C: per-chunk scan + base; dinv; zero cursors ----------------
__global__ void k_scanC() {
    __shared__ int wsum[32];
    int half = blockIdx.y;
    int idx = blockIdx.x * 1024 + threadIdx.x;
    int lane = threadIdx.x & 31, w = threadIdx.x >> 5;
    int* cnt = half ? g_cntC : g_cntP;
    int* off = half ? g_offC : g_offP;
    float* dinv = half ? g_dinvC : g_dinvP;
    int v = (idx < NN) ? cnt[idx] : 0;
    int x = v;
#pragma unroll
    for (int o = 1; o < 32; o <<= 1) {
        int y = __shfl_up_sync(0xffffffff, x, o);
        if (lane >= o) x += y;
    }
    if (lane == 31) wsum[w] = x;
    __syncthreads();
    if (w == 0) {
        int s = wsum[lane];
#pragma unroll
        for (int o = 1; o < 32; o <<= 1) {
            int y = __shfl_up_sync(0xffffffff, s, o);
            if (lane >= o) s += y;
        }
        wsum[lane] = s;
    }
    __syncthreads();
    int incl = x + (w ? wsum[w - 1] : 0);
    int excl = incl - v + g_bsum[half * NBLK + blockIdx.x];
    if (idx < NN) {
        off[idx] = excl;
        dinv[idx] = v ? (1.f / v) : 0.f;
        cnt[idx] = 0;
    }
}

// fill direction-sorted edge lists (packed int2)
__global__ void k_fill(const int* __restrict__ src, const int* __restrict__ dst) {
    int e = blockIdx.x * blockDim.x + threadIdx.x;
    if (e < NE) {
        int s = src[e], d = dst[e];
        int p = atomicAdd(&g_cntP[d], 1);
        g_eP[g_offP[d] + p] = make_int2(d, s);
        int c = atomicAdd(&g_cntC[s], 1);
        g_eC[g_offC[s] + c] = make_int2(s, d);
    }
}

// ---------------- PQ = x @ [pW1t|pW1b|cW1t|cW1b]  (first iteration only) ----------------
__global__ void k_pq_dual(const float* __restrict__ pW1, const float* __restrict__ cW1) {
    __shared__ float As[64][68];
    __shared__ float Bs[64][64];
    int tid = threadIdx.x;
    int tx = tid & 15, ty = tid >> 4;
    int nb = blockIdx.x * 64;

    for (int t = tid; t < 1024; t += 256) {
        int r = t >> 4, q = t & 15;
        float4 v = make_float4(0.f, 0.f, 0.f, 0.f);
        if (nb + r < NN) v = reinterpret_cast<const float4*>(g_x)[(nb + r) * 16 + q];
        As[r][q * 4 + 0] = v.x; As[r][q * 4 + 1] = v.y;
        As[r][q * 4 + 2] = v.z; As[r][q * 4 + 3] = v.w;
    }
    for (int cc = 0; cc < 4; cc++) {
        __syncthreads();
        const float* W = (cc < 2) ? pW1 : cW1;
        int koff = (cc & 1) ? 64 : 0;
        for (int t = tid; t < 4096; t += 256) {
            int k = t >> 6, c = t & 63;
            Bs[k][c] = W[(koff + k) * 64 + c];
        }
        __syncthreads();
        float acc[4][4] = {};
#pragma unroll 8
        for (int k = 0; k < 64; k++) {
            float a[4];
#pragma unroll
            for (int r = 0; r < 4; r++) a[r] = As[ty * 4 + r][k];
            float4 b = *reinterpret_cast<float4*>(&Bs[k][tx * 4]);
#pragma unroll
            for (int r = 0; r < 4; r++) {
                acc[r][0] += a[r] * b.x; acc[r][1] += a[r] * b.y;
                acc[r][2] += a[r] * b.z; acc[r][3] += a[r] * b.w;
            }
        }
#pragma unroll
        for (int r = 0; r < 4; r++) {
            int row = nb + ty * 4 + r;
            if (row < NN) {
                uint2 o;
                o.x = pack_h2(acc[r][0], acc[r][1]);
                o.y = pack_h2(acc[r][2], acc[r][3]);
                reinterpret_cast<uint2*>(g_PQ)[row * 64 + cc * 16 + tx] = o;
            }
        }
    }
}

// ---------------- z1 stats, one direction per block (grid.y), 4-edge unroll ----------------
__global__ void k_stats1_dual() {
    __shared__ float red[128];
    int tid = threadIdx.x;
    if (tid < 128) red[tid] = 0.f;
    __syncthreads();
    int lane = tid & 31;
    int dir = blockIdx.y;
    int gw = (blockIdx.x * blockDim.x + tid) >> 5;
    int nw = (gridDim.x * blockDim.x) >> 5;
    int chunk = (NE + nw - 1) / nw;
    int e0 = gw * chunk, e1 = min(NE, e0 + chunk);
    const unsigned* PQw = reinterpret_cast<const unsigned*>(g_PQ);  // 128 uints/row
    const int2* eL = dir ? g_eC : g_eP;
    int pb = dir * 64;   // P at col offset 0 or 64 (in uints: +0/+64), Q at +32
    float2 s = {0.f, 0.f}, q = {0.f, 0.f};

    int e = e0;
    for (; e + 4 <= e1; e += 4) {
        int2 ed[4];
#pragma unroll
        for (int u = 0; u < 4; u++) ed[u] = eL[e + u];
        float2 P[4], Q[4];
#pragma unroll
        for (int u = 0; u < 4; u++) {
            P[u] = upk(PQw[ed[u].x * 128 + pb + lane]);
            Q[u] = upk(PQw[ed[u].y * 128 + pb + 32 + lane]);
        }
#pragma unroll
        for (int u = 0; u < 4; u++) {
            float2 v;
            v.x = P[u].x + Q[u].x; v.y = P[u].y + Q[u].y;
            s.x += v.x; s.y += v.y; q.x += v.x * v.x; q.y += v.y * v.y;
        }
    }
    for (; e < e1; e++) {
        int2 ed = eL[e];
        float2 P = upk(PQw[ed.x * 128 + pb + lane]);
        float2 Q = upk(PQw[ed.y * 128 + pb + 32 + lane]);
        float2 v;
        v.x = P.x + Q.x; v.y = P.y + Q.y;
        s.x += v.x; s.y += v.y; q.x += v.x * v.x; q.y += v.y * v.y;
    }
    atomicAdd(&red[2 * lane],          s.x); atomicAdd(&red[2 * lane + 1],      s.y);
    atomicAdd(&red[64 + 2 * lane],     q.x); atomicAdd(&red[64 + 2 * lane + 1], q.y);
    __syncthreads();
    // flush: S1 at g_stats[dir*64 + c], Q1 at g_stats[128 + dir*64 + c]
    if (tid < 64)        atomicAdd(&g_stats[dir * 64 + tid], red[tid]);
    else if (tid < 128)  atomicAdd(&g_stats[128 + dir * 64 + (tid - 64)], red[tid]);
}

// ---------------- finalize BN1 ----------------
__global__ void k_fin1(const float* __restrict__ pg1, const float* __restrict__ pbe1,
                       const float* __restrict__ cg1, const float* __restrict__ cbe1) {
    int t = threadIdx.x;  // 128
    const float invE = 1.f / NE;
    if (t < 64) {
        float s = g_stats[t], q = g_stats[128 + t];
        float mu = s * invE;
        float rs = rsqrtf(q * invE - mu * mu + EPS);
        float A = pg1[t] * rs;
        g_stats[256 + t] = A;
        g_stats[384 + t] = pbe1[t] - A * mu;
        g_stats[t] = 0.f; g_stats[128 + t] = 0.f;
    } else {
        int c = t - 64;
        float s = g_stats[64 + c], q = g_stats[192 + c];
        float mu = s * invE;
        float rs = rsqrtf(q * invE - mu * mu + EPS);
        float A = cg1[c] * rs;
        g_stats[320 + c] = A;
        g_stats[448 + c] = cbe1[c] - A * mu;
        g_stats[64 + c] = 0.f; g_stats[192 + c] = 0.f;
    }
}

// ---------------- edge MLP, one direction per block (grid.y): BN1+ReLU -> fp16 MMA -> z2 + stats
// SMEM: h1h (18432B) | Bf uint2[1024] (8192B) | prm[128] | sSt[128] | sIdx[256]  = 28672B
__global__ void k_edge2_dual() {
    extern __shared__ char smraw[];
    __half* h1h = reinterpret_cast<__half*>(smraw);                  // 128*72 halfs
    uint2*  Bf  = reinterpret_cast<uint2*>(smraw + 18432);           // 1024
    float*  prm = reinterpret_cast<float*>(smraw + 18432 + 8192);    // 128
    float*  sSt = prm + 128;                                         // 128
    int*    sIdx = reinterpret_cast<int*>(sSt + 128);                // 256

    int tid = threadIdx.x;
    int lane = tid & 31;
    int wid = tid >> 5;
    int dir = blockIdx.y;
    int e0 = blockIdx.x * 128;

    if (tid < 64) {
        prm[tid]      = g_stats[256 + dir * 64 + tid];  // A1 (p or c)
        prm[64 + tid] = g_stats[384 + dir * 64 + tid];  // D1
    }
    if (tid < 128) {
        sSt[tid] = 0.f;
        int2 ep = dir ? g_eC[e0 + tid] : g_eP[e0 + tid];
        sIdx[tid]       = ep.x;
        sIdx[128 + tid] = ep.y;
    }
    // copy this direction's pre-packed fragments (8 KB) via uint4
    {
        const uint4* Bg = reinterpret_cast<const uint4*>(g_Bf) + dir * 512;
        uint4* Bs4 = reinterpret_cast<uint4*>(Bf);
#pragma unroll
        for (int t = tid; t < 512; t += 256) Bs4[t] = Bg[t];
    }
    __syncthreads();

    const uint4* PQ4 = reinterpret_cast<const uint4*>(g_PQ);  // 32 uint4/row
    int m0 = wid * 16;
    int lr = (lane & 7) + ((lane >> 3) & 1) * 8;
    int lc = (lane >> 4) * 8;
    int row0 = e0 + m0 + (lane >> 2);
    int pbase = dir * 16;

    // phase 1: h1 = relu(A*(P[i]+Q[j]) + D) stored fp16; uint4 gathers
    for (int t = tid; t < 1024; t += 256) {
        int er = t >> 3, q = t & 7;
        int i = sIdx[er], j = sIdx[128 + er];
        uint4 pu = PQ4[i * 32 + pbase + q];
        uint4 qu = PQ4[j * 32 + pbase + 8 + q];
        float2 p0 = upk(pu.x), p1 = upk(pu.y), p2 = upk(pu.z), p3 = upk(pu.w);
        float2 r0 = upk(qu.x), r1 = upk(qu.y), r2 = upk(qu.z), r3 = upk(qu.w);
        int c = q * 8;
        float h0 = fmaxf(fmaf(prm[c + 0], p0.x + r0.x, prm[64 + c + 0]), 0.f);
        float h1 = fmaxf(fmaf(prm[c + 1], p0.y + r0.y, prm[64 + c + 1]), 0.f);
        float h2 = fmaxf(fmaf(prm[c + 2], p1.x + r1.x, prm[64 + c + 2]), 0.f);
        float h3 = fmaxf(fmaf(prm[c + 3], p1.y + r1.y, prm[64 + c + 3]), 0.f);
        float h4 = fmaxf(fmaf(prm[c + 4], p2.x + r2.x, prm[64 + c + 4]), 0.f);
        float h5 = fmaxf(fmaf(prm[c + 5], p2.y + r2.y, prm[64 + c + 5]), 0.f);
        float h6 = fmaxf(fmaf(prm[c + 6], p3.x + r3.x, prm[64 + c + 6]), 0.f);
        float h7 = fmaxf(fmaf(prm[c + 7], p3.y + r3.y, prm[64 + c + 7]), 0.f);
        uint4 o;
        o.x = pack_h2(h0, h1); o.y = pack_h2(h2, h3);
        o.z = pack_h2(h4, h5); o.w = pack_h2(h6, h7);
        *reinterpret_cast<uint4*>(&h1h[er * 72 + c]) = o;
    }
    __syncthreads();

    unsigned a[4][4];
#pragma unroll
    for (int kk = 0; kk < 4; kk++) {
        unsigned addr = (unsigned)__cvta_generic_to_shared(
            &h1h[(m0 + lr) * 72 + kk * 16 + lc]);
        asm volatile("ldmatrix.sync.aligned.m8n8.x4.shared.b16 {%0,%1,%2,%3}, [%4];"
                     : "=r"(a[kk][0]), "=r"(a[kk][1]), "=r"(a[kk][2]), "=r"(a[kk][3])
                     : "r"(addr));
    }
    float acc[8][4];
#pragma unroll
    for (int nt = 0; nt < 8; nt++)
#pragma unroll
        for (int u = 0; u < 4; u++) acc[nt][u] = 0.f;

#pragma unroll
    for (int kk = 0; kk < 4; kk++) {
#pragma unroll
        for (int nt = 0; nt < 8; nt++) {
            uint2 b = Bf[(kk * 8 + nt) * 32 + lane];
            mma_f16(acc[nt], a[kk], b.x, b.y);
        }
    }

    __half* z2 = dir ? g_z2c : g_z2p;
#pragma unroll
    for (int nt = 0; nt < 8; nt++) {
        int col = nt * 8 + (lane & 3) * 2;
        __half2 hv0 = __floats2half2_rn(acc[nt][0], acc[nt][1]);
        __half2 hv1 = __floats2half2_rn(acc[nt][2], acc[nt][3]);
        *reinterpret_cast<__half2*>(&z2[row0 * 64 + col])       = hv0;
        *reinterpret_cast<__half2*>(&z2[(row0 + 8) * 64 + col]) = hv1;
        float2 r0 = __half22float2(hv0), r1 = __half22float2(hv1);
        float se = r0.x + r1.x, qe = r0.x * r0.x + r1.x * r1.x;
        float so = r0.y + r1.y, qo = r0.y * r0.y + r1.y * r1.y;
#pragma unroll
        for (int off = 4; off < 32; off <<= 1) {
            se += __shfl_xor_sync(0xffffffff, se, off);
            qe += __shfl_xor_sync(0xffffffff, qe, off);
            so += __shfl_xor_sync(0xffffffff, so, off);
            qo += __shfl_xor_sync(0xffffffff, qo, off);
        }
        if (lane < 4) {
            atomicAdd(&sSt[col], se);
            atomicAdd(&sSt[64 + col], qe);
            atomicAdd(&sSt[col + 1], so);
            atomicAdd(&sSt[64 + col + 1], qo);
        }
    }
    __syncthreads();

    // flush: sSt[0:64]=S2, sSt[64:128]=Q2 for this dir
    if (tid < 64)        atomicAdd(&g_stats[512 + dir * 64 + tid], sSt[tid]);
    else if (tid < 128)  atomicAdd(&g_stats[640 + dir * 64 + (tid - 64)], sSt[tid]);
}

// ---------------- finalize BN2 ----------------
__global__ void k_fin2(const float* __restrict__ pg2, const float* __restrict__ pbe2,
                       const float* __restrict__ cg2, const float* __restrict__ cbe2) {
    int t = threadIdx.x;  // 128
    const float invE = 1.f / NE;
    if (t < 64) {
        float s = g_stats[512 + t], q = g_stats[640 + t];
        float mu = s * invE;
        float rs = rsqrtf(q * invE - mu * mu + EPS);
        float A = pg2[t] * rs;
        g_stats[768 + t] = A;
        g_stats[896 + t] = pbe2[t] - A * mu;
        g_stats[512 + t] = 0.f; g_stats[640 + t] = 0.f;
    } else {
        int c = t - 64;
        float s = g_stats[576 + c], q = g_stats[704 + c];
        float mu = s * invE;
        float rs = rsqrtf(q * invE - mu * mu + EPS);
        float A = cg2[c] * rs;
        g_stats[832 + c] = A;
        g_stats[960 + c] = cbe2[c] - A * mu;
        g_stats[576 + c] = 0.f; g_stats[704 + c] = 0.f;
    }
}

// ---------------- streaming aggregation: one warp per node, 8-row unroll, split by dir -----
__global__ void __launch_bounds__(256) k_gagg() {
    int lane = threadIdx.x & 31;
    int n = blockIdx.x * 8 + (threadIdx.x >> 5);
    if (blockIdx.y == 0) {
        float2 A = *reinterpret_cast<const float2*>(&g_stats[768 + 2 * lane]);
        float2 D = *reinterpret_cast<const float2*>(&g_stats[896 + 2 * lane]);
        int s = g_offP[n], t = g_offP[n + 1];
        float ax = 0.f, ay = 0.f;
        int k = s;
        for (; k + 8 <= t; k += 8) {
            float2 f[8];
#pragma unroll
            for (int u = 0; u < 8; u++)
                f[u] = upk(*reinterpret_cast<const unsigned*>(&g_z2p[(k + u) * 64 + lane * 2]));
#pragma unroll
            for (int u = 0; u < 8; u++) {
                ax += fmaxf(fmaf(A.x, f[u].x, D.x), 0.f);
                ay += fmaxf(fmaf(A.y, f[u].y, D.y), 0.f);
            }
        }
        for (; k < t; k++) {
            float2 f0 = upk(*reinterpret_cast<const unsigned*>(&g_z2p[k * 64 + lane * 2]));
            ax += fmaxf(fmaf(A.x, f0.x, D.x), 0.f);
            ay += fmaxf(fmaf(A.y, f0.y, D.y), 0.f);
        }
        float di = g_dinvP[n];
        *reinterpret_cast<float2*>(&g_aggP[n * 64 + lane * 2]) = make_float2(ax * di, ay * di);
    } else {
        float2 A = *reinterpret_cast<const float2*>(&g_stats[832 + 2 * lane]);
        float2 D = *reinterpret_cast<const float2*>(&g_stats[960 + 2 * lane]);
        int s = g_offC[n], t = g_offC[n + 1];
        float ax = 0.f, ay = 0.f;
        int k = s;
        for (; k + 8 <= t; k += 8) {
            float2 f[8];
#pragma unroll
            for (int u = 0; u < 8; u++)
                f[u] = upk(*reinterpret_cast<const unsigned*>(&g_z2c[(k + u) * 64 + lane * 2]));
#pragma unroll
            for (int u = 0; u < 8; u++) {
                ax += fmaxf(fmaf(A.x, f[u].x, D.x), 0.f);
                ay += fmaxf(fmaf(A.y, f[u].y, D.y), 0.f);
            }
        }
        for (; k < t; k++) {
            float2 f0 = upk(*reinterpret_cast<const unsigned*>(&g_z2c[k * 64 + lane * 2]));
            ax += fmaxf(fmaf(A.x, f0.x, D.x), 0.f);
            ay += fmaxf(fmaf(A.y, f0.y, D.y), 0.f);
        }
        float di = g_dinvC[n];
        *reinterpret_cast<float2*>(&g_aggC[n * 64 + lane * 2]) = make_float2(ax * di, ay * di);
    }
}

// ---------------- fused node update + next-iter PQ ----------------
__global__ void k_node12(const float* __restrict__ fcW, const float* __restrict__ fcb,
                         const float* __restrict__ fc2W, const float* __restrict__ fc2b,
                         const float* __restrict__ pW1, const float* __restrict__ cW1,
                         int do_pq) {
    extern __shared__ float sm[];
    float* As   = sm;            // [64][68]
    float* Bs   = sm + 4352;     // [64][64]
    float* tmpS = sm;            // aliases As+Bs, [64][130]
    float* Bs2  = sm + 8448;     // [64][64]

    int tid = threadIdx.x, tx = tid & 15, ty = tid >> 4;
    int nb = blockIdx.x * 64;

    float acc8[4][8] = {};
    for (int kc = 0; kc < 3; kc++) {
        __syncthreads();
        for (int t = tid; t < 1024; t += 256) {
            int r = t >> 4, q = t & 15;
            int row = nb + r;
            float4 v = make_float4(0.f, 0.f, 0.f, 0.f);
            if (row < NN) {
                if (kc == 0)      v = reinterpret_cast<const float4*>(g_x)[row * 16 + q];
                else if (kc == 1) v = reinterpret_cast<const float4*>(g_aggP)[row * 16 + q];
                else              v = reinterpret_cast<const float4*>(g_aggC)[row * 16 + q];
            }
            As[r * 68 + q * 4 + 0] = v.x; As[r * 68 + q * 4 + 1] = v.y;
            As[r * 68 + q * 4 + 2] = v.z; As[r * 68 + q * 4 + 3] = v.w;
        }
        for (int cc = 0; cc < 2; cc++) {
            __syncthreads();
            for (int t = tid; t < 4096; t += 256) {
                int k = t >> 6, c = t & 63;
                Bs[k * 64 + c] = fcW[(kc * 64 + k) * 128 + cc * 64 + c];
            }
            __syncthreads();
#pragma unroll 8
            for (int k = 0; k < 64; k++) {
                float a[4];
#pragma unroll
                for (int r = 0; r < 4; r++) a[r] = As[(ty * 4 + r) * 68 + k];
                float4 b = *reinterpret_cast<float4*>(&Bs[k * 64 + tx * 4]);
#pragma unroll
                for (int r = 0; r < 4; r++) {
                    acc8[r][cc * 4 + 0] += a[r] * b.x; acc8[r][cc * 4 + 1] += a[r] * b.y;
                    acc8[r][cc * 4 + 2] += a[r] * b.z; acc8[r][cc * 4 + 3] += a[r] * b.w;
                }
            }
        }
    }
    __syncthreads();
#pragma unroll
    for (int r = 0; r < 4; r++) {
#pragma unroll
        for (int cc = 0; cc < 2; cc++) {
            int c0 = cc * 64 + tx * 4;
#pragma unroll
            for (int u = 0; u < 4; u++)
                tmpS[(ty * 4 + r) * 130 + c0 + u] =
                    fmaxf(acc8[r][cc * 4 + u] + fcb[c0 + u], 0.f);
        }
    }

    float acc2[4][4] = {};
    for (int kc = 0; kc < 2; kc++) {
        __syncthreads();
        for (int t = tid; t < 4096; t += 256) {
            int k = t >> 6, c = t & 63;
            Bs2[k * 64 + c] = fc2W[(kc * 64 + k) * 64 + c];
        }
        __syncthreads();
#pragma unroll 8
        for (int k = 0; k < 64; k++) {
            float a[4];
#pragma unroll
            for (int r = 0; r < 4; r++) a[r] = tmpS[(ty * 4 + r) * 130 + kc * 64 + k];
            float4 b = *reinterpret_cast<float4*>(&Bs2[k * 64 + tx * 4]);
#pragma unroll
            for (int r = 0; r < 4; r++) {
                acc2[r][0] += a[r] * b.x; acc2[r][1] += a[r] * b.y;
                acc2[r][2] += a[r] * b.z; acc2[r][3] += a[r] * b.w;
            }
        }
    }
    __syncthreads();

#pragma unroll
    for (int r = 0; r < 4; r++) {
        int row = nb + ty * 4 + r;
        float4 nx = make_float4(0.f, 0.f, 0.f, 0.f);
        if (row < NN) {
            float4 x0 = reinterpret_cast<float4*>(g_x)[row * 16 + tx];
            nx.x = x0.x + acc2[r][0] + fc2b[tx * 4 + 0];
            nx.y = x0.y + acc2[r][1] + fc2b[tx * 4 + 1];
            nx.z = x0.z + acc2[r][2] + fc2b[tx * 4 + 2];
            nx.w = x0.w + acc2[r][3] + fc2b[tx * 4 + 3];
            reinterpret_cast<float4*>(g_x)[row * 16 + tx] = nx;
        }
        As[(ty * 4 + r) * 68 + tx * 4 + 0] = nx.x;
        As[(ty * 4 + r) * 68 + tx * 4 + 1] = nx.y;
        As[(ty * 4 + r) * 68 + tx * 4 + 2] = nx.z;
        As[(ty * 4 + r) * 68 + tx * 4 + 3] = nx.w;
    }
    if (!do_pq) return;

    for (int cc = 0; cc < 4; cc++) {
        __syncthreads();
        const float* W = (cc < 2) ? pW1 : cW1;
        int koff = (cc & 1) ? 64 : 0;
        for (int t = tid; t < 4096; t += 256) {
            int k = t >> 6, c = t & 63;
            Bs2[k * 64 + c] = W[(koff + k) * 64 + c];
        }
        __syncthreads();
        float acc[4][4] = {};
#pragma unroll 8
        for (int k = 0; k < 64; k++) {
            float a[4];
#pragma unroll
            for (int r = 0; r < 4; r++) a[r] = As[(ty * 4 + r) * 68 + k];
            float4 b = *reinterpret_cast<float4*>(&Bs2[k * 64 + tx * 4]);
#pragma unroll
            for (int r = 0; r < 4; r++) {
                acc[r][0] += a[r] * b.x; acc[r][1] += a[r] * b.y;
                acc[r][2] += a[r] * b.z; acc[r][3] += a[r] * b.w;
            }
        }
#pragma unroll
        for (int r = 0; r < 4; r++) {
            int row = nb + ty * 4 + r;
            if (row < NN) {
                uint2 o;
                o.x = pack_h2(acc[r][0], acc[r][1]);
                o.y = pack_h2(acc[r][2], acc[r][3]);
                reinterpret_cast<uint2*>(g_PQ)[row * 64 + cc * 16 + tx] = o;
            }
        }
    }
}

// ---------------- out = x @ convW + convb ----------------
__global__ void k_out(const float* __restrict__ convW, const float* __restrict__ convb,
                      float* __restrict__ out) {
    __shared__ float As[64][68];
    __shared__ float Bs[64][64];
    int tid = threadIdx.x, tx = tid & 15, ty = tid >> 4;
    int nb = blockIdx.x * 64;

    for (int t = tid; t < 1024; t += 256) {
        int r = t >> 4, q = t & 15;
        float4 v = make_float4(0.f, 0.f, 0.f, 0.f);
        if (nb + r < NN) v = reinterpret_cast<const float4*>(g_x)[(nb + r) * 16 + q];
        As[r][q * 4 + 0] = v.x; As[r][q * 4 + 1] = v.y;
        As[r][q * 4 + 2] = v.z; As[r][q * 4 + 3] = v.w;
    }
    for (int cc = 0; cc < 2; cc++) {
        __syncthreads();
        for (int t = tid; t < 4096; t += 256) {
            int k = t >> 6, c = t & 63;
            Bs[k][c] = convW[k * 128 + cc * 64 + c];
        }
        __syncthreads();
        float acc[4][4] = {};
#pragma unroll 8
        for (int k = 0; k < 64; k++) {
            float a[4];
#pragma unroll
            for (int r = 0; r < 4; r++) a[r] = As[ty * 4 + r][k];
            float4 b = *reinterpret_cast<float4*>(&Bs[k][tx * 4]);
#pragma unroll
            for (int r = 0; r < 4; r++) {
                acc[r][0] += a[r] * b.x; acc[r][1] += a[r] * b.y;
                acc[r][2] += a[r] * b.z; acc[r][3] += a[r] * b.w;
            }
        }
#pragma unroll
        for (int r = 0; r < 4; r++) {
            int row = nb + ty * 4 + r;
            if (row < NN) {
                float4 o;
                o.x = acc[r][0] + convb[cc * 64 + tx * 4 + 0];
                o.y = acc[r][1] + convb[cc * 64 + tx * 4 + 1];
                o.z = acc[r][2] + convb[cc * 64 + tx * 4 + 2];
                o.w = acc[r][3] + convb[cc * 64 + tx * 4 + 3];
                reinterpret_cast<float4*>(out)[row * 32 + cc * 16 + tx] = o;
            }
        }
    }
}

// ---------------- host launcher ----------------
extern "C" void kernel_launch(void* const* d_in, const int* in_sizes, int n_in,
                              void* d_out, int out_size) {
    (void)in_sizes; (void)n_in; (void)out_size;
    const int*   nodes = (const int*)d_in[0];
    const int*   edges = (const int*)d_in[1];
    const int*   src   = edges;            // edges[0]
    const int*   dst   = edges + NE;       // edges[1]
    const float* emb   = (const float*)d_in[2];
    const float* pW1 = (const float*)d_in[3];
    const float* pg1 = (const float*)d_in[5],  *pbe1 = (const float*)d_in[6];
    const float* pW2 = (const float*)d_in[7];
    const float* pg2 = (const float*)d_in[9],  *pbe2 = (const float*)d_in[10];
    const float* cW1 = (const float*)d_in[11];
    const float* cg1 = (const float*)d_in[13], *cbe1 = (const float*)d_in[14];
    const float* cW2 = (const float*)d_in[15];
    const float* cg2 = (const float*)d_in[17], *cbe2 = (const float*)d_in[18];
    const float* fcW  = (const float*)d_in[19], *fcb  = (const float*)d_in[20];
    const float* fc2W = (const float*)d_in[21], *fc2b = (const float*)d_in[22];
    const float* convW = (const float*)d_in[23], *convb = (const float*)d_in[24];
    float* out = (float*)d_out;

    const int EDGE2_SMEM = 18432 + 8192 + 128 * 4 + 128 * 4 + 256 * 4;  // 28672
    const int NODE12_SMEM = (8448 + 4096) * 4;                          // 50176
    cudaFuncSetAttribute(k_edge2_dual, cudaFuncAttributeMaxDynamicSharedMemorySize, EDGE2_SMEM);
    cudaFuncSetAttribute(k_node12, cudaFuncAttributeMaxDynamicSharedMemorySize, NODE12_SMEM);

    k_zero<<<196, 256>>>();
    k_init<<<6258, 256>>>(nodes, emb, src, dst, pW2, cW2);
    {
        dim3 g(NBLK, 2);
        k_scanA<<<g, 1024>>>();
        k_scanB<<<1, 128>>>();
        k_scanC<<<g, 1024>>>();
    }
    k_fill<<<3125, 256>>>(src, dst);
    k_pq_dual<<<782, 256>>>(pW1, cW1);

    for (int it = 0; it < 2; it++) {
        {
            dim3 gs(592, 2);
            k_stats1_dual<<<gs, 512>>>();
        }
        k_fin1<<<1, 128>>>(pg1, pbe1, cg1, cbe1);
        {
            dim3 ge(6250, 2);
            k_edge2_dual<<<ge, 256, EDGE2_SMEM>>>();
        }
        k_fin2<<<1, 128>>>(pg2, pbe2, cg2, cbe2);
        {
            dim3 gg(6250, 2);
            k_gagg<<<gg, 256>>>();
        }
        k_node12<<<782, 256, NODE12_SMEM>>>(fcW, fcb, fc2W, fc2b, pW1, cW1, it == 0);
    }
    k_out<<<782, 256>>>(convW, convb, out);
}